// round 2
// baseline (speedup 1.0000x reference)
#include <cuda_runtime.h>
#include <cstdint>
#include <math.h>

#define N_IMG 4
#define CIN   512
#define COUT  512
#define PXN   2500
#define RTOT  22500
#define NSORT 32768
#define NBEF  6000
#define NAFT  300
#define WORDS 94

#define OFF_LOC   0
#define OFF_SCORE 360000
#define OFF_ROIS  540000
#define OFF_IDX   544800
#define OFF_ANC   546000

#define SMEM_HEADS (32488*4)

// ---------------- scratch (static device memory; no allocs) ----------------
__device__ float              g_inter[(size_t)N_IMG * PXN * COUT];
__device__ float              g_boxes[(size_t)N_IMG * RTOT * 4];
__device__ unsigned long long g_keys [(size_t)N_IMG * NSORT];
__device__ float              g_sboxes[(size_t)N_IMG * NBEF * 4];
__device__ unsigned char      g_valid [(size_t)N_IMG * NBEF];
__device__ unsigned long long g_mask [(size_t)N_IMG * NBEF * WORDS];

// anchor corner offsets relative to cell origin (cy=cx=8 center)
__constant__ float cAy1[9] = {-37.254833991878082f, -82.509667991878075f, -173.01933598375615f,
                              -56.0f, -120.0f, -248.0f,
                              -82.509667991878075f, -173.01933598375615f, -354.03867196751231f};
__constant__ float cAy2[9] = { 53.254833991878082f,  98.509667991878075f,  189.01933598375615f,
                               72.0f,  136.0f,  264.0f,
                               98.509667991878075f,  189.01933598375615f,  370.03867196751231f};
__constant__ float cAx1[9] = {-82.509667991878075f, -173.01933598375615f, -354.03867196751231f,
                              -56.0f, -120.0f, -248.0f,
                              -37.254833991878082f, -82.509667991878075f, -173.01933598375615f};
__constant__ float cAx2[9] = { 98.509667991878075f,  189.01933598375615f,  370.03867196751231f,
                               72.0f,  136.0f,  264.0f,
                               53.254833991878082f,  98.509667991878075f,  189.01933598375615f};

__device__ __forceinline__ unsigned long long packKey(float s, unsigned idx) {
    unsigned b = __float_as_uint(s);
    unsigned m = b ^ ((b & 0x80000000u) ? 0xFFFFFFFFu : 0x80000000u); // monotone asc transform
    return ((unsigned long long)(~m) << 32) | (unsigned long long)idx; // asc key = desc score, asc idx
}

__device__ __forceinline__ float readScalar(const unsigned* p) {
    unsigned u = *p;
    return (u < 0x10000u) ? (float)u : __uint_as_float(u);
}

// ================= conv 3x3 (implicit GEMM, fp32, 128x128x8 tiles) =================
__global__ __launch_bounds__(256, 2)
void conv3x3_relu(const float* __restrict__ X, const float* __restrict__ W,
                  const float* __restrict__ Bv) {
    const int n = blockIdx.z, bm = blockIdx.y, bn = blockIdx.x;
    __shared__ float As[2][8][128];
    __shared__ float Bs[2][8][128];
    const int tid = threadIdx.x;
    const int tx = tid & 15, ty = tid >> 4;
    const int arow = tid >> 1, ahalf = (tid & 1) * 4;
    const int bkk = tid >> 5, bp = (tid & 31) * 4;
    const float* Aptr = W + (size_t)(bm * 128 + arow) * 4608 + ahalf;

    float acc[8][8];
#pragma unroll
    for (int i = 0; i < 8; i++)
#pragma unroll
        for (int j = 0; j < 8; j++) acc[i][j] = 0.f;

    // preload chunk 0
    {
        float4 av = *(const float4*)(Aptr);
        As[0][ahalf + 0][arow] = av.x; As[0][ahalf + 1][arow] = av.y;
        As[0][ahalf + 2][arow] = av.z; As[0][ahalf + 3][arow] = av.w;
        int k = bkk;
        int c = k / 9; int r9 = k - c * 9; int ky = r9 / 3; int kx = r9 - ky * 3;
        const float* xc = X + (size_t)(n * 512 + c) * 2500;
        float bv[4];
#pragma unroll
        for (int e = 0; e < 4; e++) {
            int p = bn * 128 + bp + e;
            float v = 0.f;
            if (p < 2500) {
                int y = p / 50; int x = p - y * 50;
                int sy = y + ky - 1, sx = x + kx - 1;
                if ((unsigned)sy < 50u && (unsigned)sx < 50u) v = xc[sy * 50 + sx];
            }
            bv[e] = v;
        }
        *(float4*)&Bs[0][bkk][bp] = make_float4(bv[0], bv[1], bv[2], bv[3]);
    }
    __syncthreads();

    float4 aN; float bN[4];
    for (int t = 0; t < 576; t++) {
        int cur = t & 1;
        if (t < 575) {
            int k0 = (t + 1) * 8;
            aN = *(const float4*)(Aptr + k0);
            int k = k0 + bkk;
            int c = k / 9; int r9 = k - c * 9; int ky = r9 / 3; int kx = r9 - ky * 3;
            const float* xc = X + (size_t)(n * 512 + c) * 2500;
#pragma unroll
            for (int e = 0; e < 4; e++) {
                int p = bn * 128 + bp + e;
                float v = 0.f;
                if (p < 2500) {
                    int y = p / 50; int x = p - y * 50;
                    int sy = y + ky - 1, sx = x + kx - 1;
                    if ((unsigned)sy < 50u && (unsigned)sx < 50u) v = xc[sy * 50 + sx];
                }
                bN[e] = v;
            }
        }
#pragma unroll
        for (int kk = 0; kk < 8; kk++) {
            float a[8], b[8];
            *(float4*)(a)     = *(float4*)(&As[cur][kk][ty * 8]);
            *(float4*)(a + 4) = *(float4*)(&As[cur][kk][ty * 8 + 4]);
            *(float4*)(b)     = *(float4*)(&Bs[cur][kk][tx * 8]);
            *(float4*)(b + 4) = *(float4*)(&Bs[cur][kk][tx * 8 + 4]);
#pragma unroll
            for (int i = 0; i < 8; i++)
#pragma unroll
                for (int j = 0; j < 8; j++) acc[i][j] += a[i] * b[j];
        }
        if (t < 575) {
            int nx = cur ^ 1;
            As[nx][ahalf + 0][arow] = aN.x; As[nx][ahalf + 1][arow] = aN.y;
            As[nx][ahalf + 2][arow] = aN.z; As[nx][ahalf + 3][arow] = aN.w;
            *(float4*)&Bs[nx][bkk][bp] = make_float4(bN[0], bN[1], bN[2], bN[3]);
            __syncthreads();
        }
    }

    float bias[8];
#pragma unroll
    for (int i = 0; i < 8; i++) bias[i] = Bv[bm * 128 + ty * 8 + i];
#pragma unroll
    for (int j = 0; j < 8; j++) {
        int p = bn * 128 + tx * 8 + j;
        if (p < 2500) {
            float* dst = g_inter + ((size_t)(n * 2500 + p)) * 512 + bm * 128 + ty * 8;
            float4 o1, o2;
            o1.x = fmaxf(acc[0][j] + bias[0], 0.f);
            o1.y = fmaxf(acc[1][j] + bias[1], 0.f);
            o1.z = fmaxf(acc[2][j] + bias[2], 0.f);
            o1.w = fmaxf(acc[3][j] + bias[3], 0.f);
            o2.x = fmaxf(acc[4][j] + bias[4], 0.f);
            o2.y = fmaxf(acc[5][j] + bias[5], 0.f);
            o2.z = fmaxf(acc[6][j] + bias[6], 0.f);
            o2.w = fmaxf(acc[7][j] + bias[7], 0.f);
            *(float4*)dst = o1;
            *(float4*)(dst + 4) = o2;
        }
    }
}

// ================= key padding =================
__global__ void fill_keys() {
    int t = blockIdx.x * blockDim.x + threadIdx.x;
    if (t < N_IMG * NSORT) g_keys[t] = ~0ull;
}

// ================= heads: 1x1 convs + softmax + decode + keys =================
__global__ __launch_bounds__(448)
void heads_kernel(const float* __restrict__ WS, const float* __restrict__ BS,
                  const float* __restrict__ WL, const float* __restrict__ BL,
                  float* __restrict__ out,
                  const unsigned* __restrict__ pimh, const unsigned* __restrict__ pimw) {
    extern __shared__ float sm[];
    float* wsm = sm;            // 54 rows, stride 516
    float* vsm = sm + 27864;    // 8 rows, stride 516
    float* bsm = sm + 31992;    // 64
    float* res = sm + 32056;    // 8*54
    const int t = threadIdx.x;
    const int gp0 = blockIdx.x * 8;

    for (int i = t; i < 18 * 512; i += 448) { int r = i >> 9, c = i & 511; wsm[r * 516 + c] = WS[i]; }
    for (int i = t; i < 36 * 512; i += 448) { int r = i >> 9, c = i & 511; wsm[(18 + r) * 516 + c] = WL[i]; }
    if (t < 18) bsm[t] = BS[t]; else if (t < 54) bsm[t] = BL[t - 18];
    for (int i = t; i < 8 * 512; i += 448) {
        int p = i >> 9, c = i & 511;
        int gp = gp0 + p;
        vsm[p * 516 + c] = (gp < 10000) ? g_inter[(size_t)gp * 512 + c] : 0.f;
    }
    __syncthreads();

    if (t < 432) {
        int o = t >> 3, px = t & 7;
        const float4* wv = (const float4*)(wsm + o * 516);
        const float4* vv = (const float4*)(vsm + px * 516);
        float acc = 0.f;
#pragma unroll 8
        for (int q = 0; q < 128; q++) {
            float4 w4 = wv[q], v4 = vv[q];
            acc += w4.x * v4.x + w4.y * v4.y + w4.z * v4.z + w4.w * v4.w;
        }
        res[px * 54 + o] = acc + bsm[o];
    }
    __syncthreads();

    if (t < 72) {
        int px = t / 9, a = t - px * 9;
        int gp = gp0 + px;
        if (gp < 10000) {
            float imh = readScalar(pimh), imw = readScalar(pimw);
            const float* rr = res + px * 54;
            int n = gp / 2500, p = gp - n * 2500;
            int y = p / 50, x = p - y * 50;
            float s0 = rr[2 * a], s1 = rr[2 * a + 1];
            float d0 = rr[18 + 4 * a + 0], d1 = rr[18 + 4 * a + 1];
            float d2 = rr[18 + 4 * a + 2], d3 = rr[18 + 4 * a + 3];
            float yy = (float)(y * 16), xx = (float)(x * 16);
            float ay1 = yy + cAy1[a], ay2 = yy + cAy2[a];
            float ax1 = xx + cAx1[a], ax2 = xx + cAx2[a];
            float ah = ay2 - ay1, aw = ax2 - ax1;
            float acy = ay1 + 0.5f * ah, acx = ax1 + 0.5f * aw;
            float cy = d0 * ah + acy, cx = d1 * aw + acx;
            float bh = expf(d2) * ah, bw = expf(d3) * aw;
            float y1 = fminf(fmaxf(cy - 0.5f * bh, 0.f), imh);
            float y2 = fminf(fmaxf(cy + 0.5f * bh, 0.f), imh);
            float x1 = fminf(fmaxf(cx - 0.5f * bw, 0.f), imw);
            float x2 = fminf(fmaxf(cx + 0.5f * bw, 0.f), imw);
            bool valid = ((y2 - y1) >= 16.f) && ((x2 - x1) >= 16.f);
            float fg = 1.f / (1.f + expf(s0 - s1));
            int ridx = p * 9 + a;
            int gi = n * 22500 + ridx;
            out[OFF_LOC + (size_t)gi * 4 + 0] = d0;
            out[OFF_LOC + (size_t)gi * 4 + 1] = d1;
            out[OFF_LOC + (size_t)gi * 4 + 2] = d2;
            out[OFF_LOC + (size_t)gi * 4 + 3] = d3;
            out[OFF_SCORE + (size_t)gi * 2 + 0] = s0;
            out[OFF_SCORE + (size_t)gi * 2 + 1] = s1;
            float* bx = g_boxes + (size_t)gi * 4;
            bx[0] = y1; bx[1] = x1; bx[2] = y2; bx[3] = x2;
            float sc = valid ? fg : __int_as_float(0xff800000);
            g_keys[(size_t)n * NSORT + ridx] = packKey(sc, (unsigned)ridx);
        }
    }
}

// ================= anchors =================
__global__ void write_anchors(float* __restrict__ out) {
    int r = blockIdx.x * 256 + threadIdx.x;
    if (r < RTOT) {
        int a = r % 9; int pix = r / 9;
        int y = pix / 50, x = pix - y * 50;
        float yy = (float)(y * 16), xx = (float)(x * 16);
        out[OFF_ANC + (size_t)r * 4 + 0] = yy + cAy1[a];
        out[OFF_ANC + (size_t)r * 4 + 1] = xx + cAx1[a];
        out[OFF_ANC + (size_t)r * 4 + 2] = yy + cAy2[a];
        out[OFF_ANC + (size_t)r * 4 + 3] = xx + cAx2[a];
    }
}

// ================= bitonic sort (per-image 32768 keys) =================
__global__ __launch_bounds__(1024)
void sort_local() {
    __shared__ unsigned long long s[4096];
    int chunk = blockIdx.x; int img = chunk >> 3; int cb = (chunk & 7) * 4096;
    unsigned long long* g = g_keys + (size_t)img * NSORT + cb;
    int t = threadIdx.x;
#pragma unroll
    for (int q = 0; q < 4; q++) s[t + q * 1024] = g[t + q * 1024];
    __syncthreads();
    for (int k = 2; k <= 4096; k <<= 1) {
        for (int j = k >> 1; j > 0; j >>= 1) {
#pragma unroll
            for (int q = 0; q < 2; q++) {
                int pid = t + q * 1024;
                int i = ((pid & ~(j - 1)) << 1) | (pid & (j - 1));
                int pr = i | j;
                bool asc = (((cb + i) & k) == 0);
                unsigned long long a = s[i], b = s[pr];
                if ((a > b) == asc) { s[i] = b; s[pr] = a; }
            }
            __syncthreads();
        }
    }
#pragma unroll
    for (int q = 0; q < 4; q++) g[t + q * 1024] = s[t + q * 1024];
}

__global__ void sort_gstep(int k, int j) {
    int t = blockIdx.x * blockDim.x + threadIdx.x;   // 65536 threads
    int n = t >> 14; int tt = t & 16383;
    int i = ((tt & ~(j - 1)) << 1) | (tt & (j - 1));
    bool asc = ((i & k) == 0);
    unsigned long long* g = g_keys + (size_t)n * NSORT;
    unsigned long long a = g[i], b = g[i | j];
    if ((a > b) == asc) { g[i] = b; g[i | j] = a; }
}

__global__ __launch_bounds__(1024)
void sort_lfinish(int k) {
    __shared__ unsigned long long s[4096];
    int chunk = blockIdx.x; int img = chunk >> 3; int cb = (chunk & 7) * 4096;
    unsigned long long* g = g_keys + (size_t)img * NSORT + cb;
    int t = threadIdx.x;
#pragma unroll
    for (int q = 0; q < 4; q++) s[t + q * 1024] = g[t + q * 1024];
    __syncthreads();
    bool asc = ((cb & k) == 0);
    for (int j = 2048; j > 0; j >>= 1) {
#pragma unroll
        for (int q = 0; q < 2; q++) {
            int pid = t + q * 1024;
            int i = ((pid & ~(j - 1)) << 1) | (pid & (j - 1));
            int pr = i | j;
            unsigned long long a = s[i], b = s[pr];
            if ((a > b) == asc) { s[i] = b; s[pr] = a; }
        }
        __syncthreads();
    }
#pragma unroll
    for (int q = 0; q < 4; q++) g[t + q * 1024] = s[t + q * 1024];
}

// ================= gather top-6000 =================
__global__ void gather_top() {
    int t = blockIdx.x * blockDim.x + threadIdx.x;
    if (t >= N_IMG * NBEF) return;
    int n = t / NBEF;
    unsigned long long key = g_keys[(size_t)n * NSORT + (t - n * NBEF)];
    unsigned idx = (unsigned)key;
    unsigned hi = (unsigned)(key >> 32);
    bool valid = hi < 0x80000000u;   // finite score
    float4 b = make_float4(0, 0, 0, 0);
    if (idx < RTOT) b = *(const float4*)(g_boxes + ((size_t)n * RTOT + idx) * 4);
    *(float4*)(g_sboxes + (size_t)t * 4) = b;
    g_valid[t] = valid ? 1 : 0;
}

// ================= NMS bitmask =================
__global__ __launch_bounds__(64)
void nms_mask() {
    int cb = blockIdx.x, rb = blockIdx.y, n = blockIdx.z;
    int t = threadIdx.x;
    int i = rb * 64 + t;
    if (cb < rb) {
        if (i < NBEF) g_mask[((size_t)(n * NBEF) + i) * WORDS + cb] = 0ull;
        return;
    }
    __shared__ float4 cbox[64];
    int j0 = cb * 64;
    float4 b = make_float4(0, 0, 0, 0);
    if (j0 + t < NBEF) b = *(const float4*)(g_sboxes + ((size_t)n * NBEF + j0 + t) * 4);
    cbox[t] = b;
    __syncthreads();
    if (i >= NBEF) return;
    float4 r = *(const float4*)(g_sboxes + ((size_t)n * NBEF + i) * 4);
    float ra = (r.z - r.x) * (r.w - r.y);
    unsigned long long m = 0;
#pragma unroll 8
    for (int c = 0; c < 64; c++) {
        int j = j0 + c;
        float4 q = cbox[c];
        float ty = fmaxf(r.x, q.x), tx = fmaxf(r.y, q.y);
        float by = fminf(r.z, q.z), bx = fminf(r.w, q.w);
        float inter = fmaxf(by - ty, 0.f) * fmaxf(bx - tx, 0.f);
        float qa = (q.z - q.x) * (q.w - q.y);
        float iou = inter / (ra + qa - inter + 1e-9f);
        if (j > i && iou > 0.7f) m |= (1ull << c);
    }
    g_mask[((size_t)(n * NBEF) + i) * WORDS + cb] = m;
}

// ================= NMS serial scan (1 warp per image) =================
__global__ void nms_scan(float* __restrict__ out) {
    int n = blockIdx.x; int lane = threadIdx.x;
    unsigned long long rem[3] = {0, 0, 0};
    __shared__ int kl[NAFT];
    int kc = 0;
    for (int i = 0; i < NBEF && kc < NAFT; ++i) {
        int wi = i >> 6; int slot = wi >> 5; int owner = wi & 31;
        unsigned long long myw = (slot == 0) ? rem[0] : ((slot == 1) ? rem[1] : rem[2]);
        unsigned long long w = __shfl_sync(0xffffffffu, myw, owner);
        bool removed = (w >> (i & 63)) & 1ull;
        if (!removed && g_valid[(size_t)n * NBEF + i]) {
            if (lane == 0) kl[kc] = i;
            kc++;
            const unsigned long long* mr = g_mask + ((size_t)(n * NBEF) + i) * WORDS;
#pragma unroll
            for (int s = 0; s < 3; s++) {
                int ww = lane + 32 * s;
                if (ww < WORDS) rem[s] |= mr[ww];
            }
        }
    }
    __syncwarp();
    for (int r = lane; r < NAFT; r += 32) {
        float4 b = make_float4(0, 0, 0, 0);
        if (r < kc) b = *(const float4*)(g_sboxes + ((size_t)n * NBEF + kl[r]) * 4);
        float* dst = out + OFF_ROIS + (size_t)(n * NAFT + r) * 4;
        dst[0] = b.x; dst[1] = b.y; dst[2] = b.z; dst[3] = b.w;
        out[OFF_IDX + n * NAFT + r] = (float)n;
    }
}

// ================= launch =================
extern "C" void kernel_launch(void* const* d_in, const int* in_sizes, int n_in,
                              void* d_out, int out_size) {
    const float* x  = (const float*)d_in[0];
    const float* w1 = (const float*)d_in[1];
    const float* b1 = (const float*)d_in[2];
    const float* ws = (const float*)d_in[3];
    const float* bs = (const float*)d_in[4];
    const float* wl = (const float*)d_in[5];
    const float* bl = (const float*)d_in[6];
    const unsigned* ih = (const unsigned*)d_in[7];
    const unsigned* iw = (const unsigned*)d_in[8];
    float* out = (float*)d_out;

    cudaFuncSetAttribute(heads_kernel, cudaFuncAttributeMaxDynamicSharedMemorySize, SMEM_HEADS);

    conv3x3_relu<<<dim3(20, 4, 4), 256>>>(x, w1, b1);
    fill_keys<<<512, 256>>>();
    heads_kernel<<<1250, 448, SMEM_HEADS>>>(ws, bs, wl, bl, out, ih, iw);
    write_anchors<<<88, 256>>>(out);

    sort_local<<<32, 1024>>>();
    sort_gstep<<<256, 256>>>(8192, 4096);
    sort_lfinish<<<32, 1024>>>(8192);
    sort_gstep<<<256, 256>>>(16384, 8192);
    sort_gstep<<<256, 256>>>(16384, 4096);
    sort_lfinish<<<32, 1024>>>(16384);
    sort_gstep<<<256, 256>>>(32768, 16384);
    sort_gstep<<<256, 256>>>(32768, 8192);
    sort_gstep<<<256, 256>>>(32768, 4096);
    sort_lfinish<<<32, 1024>>>(32768);

    gather_top<<<94, 256>>>();
    nms_mask<<<dim3(WORDS, WORDS, N_IMG), 64>>>();
    nms_scan<<<N_IMG, 32>>>(out);
}

// round 6
// speedup vs baseline: 1.4633x; 1.4633x over previous
#include <cuda_runtime.h>
#include <cuda_fp16.h>
#include <cstdint>
#include <math.h>

#define N_IMG 4
#define PXN   2500
#define NPAD  2560
#define RTOT  22500
#define NSORT 32768
#define NBEF  6000
#define NAFT  300
#define WORDS 94

#define OFF_LOC   0
#define OFF_SCORE 360000
#define OFF_ROIS  540000
#define OFF_IDX   544800
#define OFF_ANC   546000

#define KREAL 4608
#define KVIRT 27648
#define KCHUNK 64
#define NCHUNK 432
#define ASTG 16384
#define BSTG 16384
#define STGB (ASTG + BSTG)
#define SMEM_CONV (3 * STGB)          // 98304; also covers 128*129*4 transpose buf
#define SMEM_HEADS (32488*4)

#define SC1 2048.0f                   // 2^11
#define SC1I 4.8828125e-4f            // 2^-11
#define SC2 4194304.0f                // 2^22
#define SC2I 2.384185791015625e-7f    // 2^-22

// ---------------- scratch (static device memory; no allocs) ----------------
__device__ __align__(1024) __half g_aprime[(size_t)512 * KVIRT];
__device__ __align__(1024) __half g_bh[(size_t)N_IMG * NPAD * KREAL];
__device__ __align__(1024) __half g_bm[(size_t)N_IMG * NPAD * KREAL];
__device__ __align__(1024) __half g_bl[(size_t)N_IMG * NPAD * KREAL];
__device__ float              g_inter[(size_t)N_IMG * PXN * 512];
__device__ float              g_boxes[(size_t)N_IMG * RTOT * 4];
__device__ unsigned long long g_keys [(size_t)N_IMG * NSORT];
__device__ float              g_sboxes[(size_t)N_IMG * NBEF * 4];
__device__ unsigned char      g_valid [(size_t)N_IMG * NBEF];
__device__ unsigned long long g_mask [(size_t)N_IMG * NBEF * WORDS];

__constant__ float cAy1[9] = {-37.254833991878082f, -82.509667991878075f, -173.01933598375615f,
                              -56.0f, -120.0f, -248.0f,
                              -82.509667991878075f, -173.01933598375615f, -354.03867196751231f};
__constant__ float cAy2[9] = { 53.254833991878082f,  98.509667991878075f,  189.01933598375615f,
                               72.0f,  136.0f,  264.0f,
                               98.509667991878075f,  189.01933598375615f,  370.03867196751231f};
__constant__ float cAx1[9] = {-82.509667991878075f, -173.01933598375615f, -354.03867196751231f,
                              -56.0f, -120.0f, -248.0f,
                              -37.254833991878082f, -82.509667991878075f, -173.01933598375615f};
__constant__ float cAx2[9] = { 98.509667991878075f,  189.01933598375615f,  370.03867196751231f,
                               72.0f,  136.0f,  264.0f,
                               53.254833991878082f,  98.509667991878075f,  189.01933598375615f};

// ---------------- helpers ----------------
__device__ __forceinline__ uint32_t smem_u32(const void* p) {
    uint32_t a;
    asm("{ .reg .u64 t; cvta.to.shared.u64 t, %1; cvt.u32.u64 %0, t; }" : "=r"(a) : "l"(p));
    return a;
}
__device__ __forceinline__ void cpa16(uint32_t d, const void* s) {
    asm volatile("cp.async.cg.shared.global [%0], [%1], 16;" :: "r"(d), "l"(s) : "memory");
}
#define LDSM_X4(r, addr) \
    asm volatile("ldmatrix.sync.aligned.m8n8.x4.shared.b16 {%0,%1,%2,%3}, [%4];" \
        : "=r"((r)[0]), "=r"((r)[1]), "=r"((r)[2]), "=r"((r)[3]) : "r"(addr))
__device__ __forceinline__ void mma16816(float* c, const uint32_t* a, const uint32_t* b) {
    asm volatile("mma.sync.aligned.m16n8k16.row.col.f32.f16.f16.f32 "
        "{%0,%1,%2,%3}, {%4,%5,%6,%7}, {%8,%9}, {%0,%1,%2,%3};"
        : "+f"(c[0]), "+f"(c[1]), "+f"(c[2]), "+f"(c[3])
        : "r"(a[0]), "r"(a[1]), "r"(a[2]), "r"(a[3]), "r"(b[0]), "r"(b[1]));
}
// d = a*b + 0   (fresh accumulator per chunk)
__device__ __forceinline__ void mma16816_z(float* d, const uint32_t* a, const uint32_t* b) {
    asm volatile("mma.sync.aligned.m16n8k16.row.col.f32.f16.f16.f32 "
        "{%0,%1,%2,%3}, {%4,%5,%6,%7}, {%8,%9}, {%10,%11,%12,%13};"
        : "=f"(d[0]), "=f"(d[1]), "=f"(d[2]), "=f"(d[3])
        : "r"(a[0]), "r"(a[1]), "r"(a[2]), "r"(a[3]), "r"(b[0]), "r"(b[1]),
          "f"(0.f), "f"(0.f), "f"(0.f), "f"(0.f));
}

__device__ __forceinline__ unsigned long long packKey(float s, unsigned idx) {
    unsigned b = __float_as_uint(s);
    unsigned m = b ^ ((b & 0x80000000u) ? 0xFFFFFFFFu : 0x80000000u);
    return ((unsigned long long)(~m) << 32) | (unsigned long long)idx;
}
__device__ __forceinline__ float readScalar(const unsigned* p) {
    unsigned u = *p;
    return (u < 0x10000u) ? (float)u : __uint_as_float(u);
}

// 3-way scaled split: v = h + 2^-11 m + 2^-22 l, all parts fp16-normal range
__device__ __forceinline__ void split3(float v, __half& h, __half& m, __half& l) {
    h = __float2half_rn(v);
    float r1 = v - __half2float(h);
    m = __float2half_rn(r1 * SC1);
    float r2 = r1 - __half2float(m) * SC1I;
    l = __float2half_rn(r2 * SC2);
}

// ================= weight split: A' = [h|h|h|m|m|l] blocks, 512 x 27648 fp16 =================
__global__ void wsplit(const float* __restrict__ W) {
    int idx = blockIdx.x * 256 + threadIdx.x;           // 512*3456 = 1769472
    if (idx >= 512 * (KVIRT / 8)) return;
    int m = idx / (KVIRT / 8), kg = idx - m * (KVIRT / 8);
    int kp = kg * 8;
    int blk = kp / KREAL;
    int k = kp - blk * KREAL;
    const float* src = W + (size_t)m * KREAL + k;
    __half o[8];
#pragma unroll
    for (int e = 0; e < 8; e++) {
        __half h, mm, l;
        split3(src[e], h, mm, l);
        o[e] = (blk < 3) ? h : ((blk < 5) ? mm : l);
    }
    *(uint4*)(g_aprime + (size_t)m * KVIRT + kp) = *(uint4*)o;
}

// ================= im2col + 3-way split =================
__global__ void im2col_split(const float* __restrict__ X) {
    int idx = blockIdx.x * 256 + threadIdx.x;
    if (idx >= N_IMG * NPAD * (KREAL / 8)) return;
    int kg = idx % (KREAL / 8);
    int rest = idx / (KREAL / 8);
    int p = rest % NPAD;
    int img = rest / NPAD;
    __half hb[8], mb[8], lb[8];
    if (p < PXN) {
        int y = p / 50, x = p - y * 50;
#pragma unroll
        for (int e = 0; e < 8; e++) {
            int k = kg * 8 + e;
            int c = k / 9; int r9 = k - c * 9; int ky = r9 / 3; int kx = r9 - ky * 3;
            int sy = y + ky - 1, sx = x + kx - 1;
            float v = 0.f;
            if ((unsigned)sy < 50u && (unsigned)sx < 50u)
                v = X[((size_t)(img * 512 + c)) * 2500 + sy * 50 + sx];
            split3(v, hb[e], mb[e], lb[e]);
        }
    } else {
#pragma unroll
        for (int e = 0; e < 8; e++) {
            hb[e] = __ushort_as_half(0); mb[e] = __ushort_as_half(0); lb[e] = __ushort_as_half(0);
        }
    }
    size_t base = ((size_t)img * NPAD + p) * KREAL + kg * 8;
    *(uint4*)(g_bh + base) = *(uint4*)hb;
    *(uint4*)(g_bm + base) = *(uint4*)mb;
    *(uint4*)(g_bl + base) = *(uint4*)lb;
}

// ================= HMMA conv GEMM: 6-product scaled split, K=27648 =================
// grid (4 m-tiles, 20 n-tiles, 4 img), 256 threads (8 warps, 2x4 warp grid)
__global__ void __launch_bounds__(256, 2) conv_mma(const float* __restrict__ bias) {
    extern __shared__ char dsm[];
    __shared__ float sbias[128];
    const int tid = threadIdx.x;
    const int wid = tid >> 5, lane = tid & 31;
    const int bm = blockIdx.x, bn = blockIdx.y, img = blockIdx.z;
    const int warp_m = wid >> 2, warp_n = wid & 3;
    const uint32_t base = smem_u32(dsm);

    if (tid < 128) sbias[tid] = bias[bm * 128 + tid];

    const __half* gA = g_aprime + (size_t)(bm * 128) * KVIRT;
    const size_t brow = ((size_t)img * NPAD + bn * 128) * KREAL;

    float acc[4][4][4];
#pragma unroll
    for (int i = 0; i < 4; i++)
#pragma unroll
        for (int j = 0; j < 4; j++)
#pragma unroll
            for (int e = 0; e < 4; e++) acc[i][j][e] = 0.f;

    const int lr = tid >> 3, lc = tid & 7;
    const int lcs = ((lc ^ (lr & 7)) * 16);

    const int ra = warp_m * 64 + (lane & 15);
    const int kha = (lane >> 4);
    const int xa = ra & 7;
    const int q8 = lane >> 3;
    const int xb = lane & 7;

#define LOAD_STAGE(T, S) do { \
    uint32_t sa_ = base + (S) * STGB; \
    int k0_ = (T) * KCHUNK; \
    const __half* gAr_ = gA + k0_ + lc * 8; \
    _Pragma("unroll") \
    for (int i_ = 0; i_ < 4; i_++) { \
        int r_ = lr + 32 * i_; \
        cpa16(sa_ + r_ * 128 + lcs, gAr_ + (size_t)r_ * KVIRT); \
    } \
    int blk_ = (T) / 72; \
    int kr_ = ((T) - blk_ * 72) * KCHUNK; \
    const __half* gBsel_ = (blk_ == 2) ? g_bl : ((blk_ == 1 || blk_ == 4) ? g_bm : g_bh); \
    const __half* gBr_ = gBsel_ + brow + kr_ + lc * 8; \
    uint32_t sb_ = sa_ + ASTG; \
    _Pragma("unroll") \
    for (int i_ = 0; i_ < 4; i_++) { \
        int r_ = lr + 32 * i_; \
        cpa16(sb_ + r_ * 128 + lcs, gBr_ + (size_t)r_ * KREAL); \
    } \
    asm volatile("cp.async.commit_group;" ::: "memory"); \
} while (0)

    LOAD_STAGE(0, 0);
    LOAD_STAGE(1, 1);

    int sCmp = 0, sLoad = 2;
    for (int t = 0; t < NCHUNK; t++) {
        if (t < NCHUNK - 2) asm volatile("cp.async.wait_group 1;" ::: "memory");
        else                asm volatile("cp.async.wait_group 0;" ::: "memory");
        __syncthreads();

        int blkc = t / 72;
        float cscale = (blkc == 0) ? 1.f
                     : ((blkc == 1 || blkc == 3) ? SC1I : SC2I);

        uint32_t sa = base + sCmp * STGB;
        uint32_t sb = sa + ASTG;
#pragma unroll
        for (int mt = 0; mt < 4; mt++) {
            uint32_t a[4][4];
            const int rA = ra + mt * 16;
#pragma unroll
            for (int kk = 0; kk < 4; kk++)
                LDSM_X4(a[kk], sa + rA * 128 + (((kk * 2 + kha) ^ xa) * 16));
#pragma unroll
            for (int nt = 0; nt < 4; nt++) {
                const int rB = warp_n * 32 + nt * 8 + xb;
                uint32_t b[8];
                LDSM_X4(b,     sb + rB * 128 + (((0 + q8) ^ xb) * 16));
                LDSM_X4(b + 4, sb + rB * 128 + (((4 + q8) ^ xb) * 16));
                float tmp[4];
                mma16816_z(tmp, a[0], b);
                mma16816(tmp, a[1], b + 2);
                mma16816(tmp, a[2], b + 4);
                mma16816(tmp, a[3], b + 6);
#pragma unroll
                for (int e = 0; e < 4; e++)
                    acc[mt][nt][e] = fmaf(tmp[e], cscale, acc[mt][nt][e]);
            }
        }

        if (t + 2 < NCHUNK) LOAD_STAGE(t + 2, sLoad);
        if (++sLoad == 3) sLoad = 0;
        if (++sCmp == 3) sCmp = 0;
    }

    // epilogue: transpose through smem (stride 129), bias + relu, coalesced store
    __syncthreads();
    float* tb = (float*)dsm;
#pragma unroll
    for (int mt = 0; mt < 4; mt++)
#pragma unroll
        for (int nt = 0; nt < 4; nt++) {
            int m = warp_m * 64 + mt * 16 + (lane >> 2);
            int n = warp_n * 32 + nt * 8 + 2 * (lane & 3);
            tb[m * 129 + n]           = acc[mt][nt][0];
            tb[m * 129 + n + 1]       = acc[mt][nt][1];
            tb[(m + 8) * 129 + n]     = acc[mt][nt][2];
            tb[(m + 8) * 129 + n + 1] = acc[mt][nt][3];
        }
    __syncthreads();

    const int j = tid >> 1, half = tid & 1;
    const int p = bn * 128 + j;
    if (p < PXN) {
        float* dst = g_inter + ((size_t)(img * PXN + p)) * 512 + bm * 128 + half * 64;
#pragma unroll
        for (int i = 0; i < 16; i++) {
            int m0 = half * 64 + i * 4;
            float4 v;
            v.x = fmaxf(tb[(m0 + 0) * 129 + j] + sbias[m0 + 0], 0.f);
            v.y = fmaxf(tb[(m0 + 1) * 129 + j] + sbias[m0 + 1], 0.f);
            v.z = fmaxf(tb[(m0 + 2) * 129 + j] + sbias[m0 + 2], 0.f);
            v.w = fmaxf(tb[(m0 + 3) * 129 + j] + sbias[m0 + 3], 0.f);
            *(float4*)(dst + i * 4) = v;
        }
    }
#undef LOAD_STAGE
}

// ================= key padding =================
__global__ void fill_keys() {
    int t = blockIdx.x * blockDim.x + threadIdx.x;
    if (t < N_IMG * NSORT) g_keys[t] = ~0ull;
}

// ================= heads =================
__global__ __launch_bounds__(448)
void heads_kernel(const float* __restrict__ WS, const float* __restrict__ BS,
                  const float* __restrict__ WL, const float* __restrict__ BL,
                  float* __restrict__ out,
                  const unsigned* __restrict__ pimh, const unsigned* __restrict__ pimw) {
    extern __shared__ float sm[];
    float* wsm = sm;            // 54 rows, stride 516
    float* vsm = sm + 27864;    // 8 rows, stride 516
    float* bsm = sm + 31992;
    float* res = sm + 32056;
    const int t = threadIdx.x;
    const int gp0 = blockIdx.x * 8;

    for (int i = t; i < 18 * 512; i += 448) { int r = i >> 9, c = i & 511; wsm[r * 516 + c] = WS[i]; }
    for (int i = t; i < 36 * 512; i += 448) { int r = i >> 9, c = i & 511; wsm[(18 + r) * 516 + c] = WL[i]; }
    if (t < 18) bsm[t] = BS[t]; else if (t < 54) bsm[t] = BL[t - 18];
    for (int i = t; i < 8 * 512; i += 448) {
        int p = i >> 9, c = i & 511;
        int gp = gp0 + p;
        vsm[p * 516 + c] = (gp < 10000) ? g_inter[(size_t)gp * 512 + c] : 0.f;
    }
    __syncthreads();

    if (t < 432) {
        int o = t >> 3, px = t & 7;
        const float4* wv = (const float4*)(wsm + o * 516);
        const float4* vv = (const float4*)(vsm + px * 516);
        float acc = 0.f;
#pragma unroll 8
        for (int q = 0; q < 128; q++) {
            float4 w4 = wv[q], v4 = vv[q];
            acc += w4.x * v4.x + w4.y * v4.y + w4.z * v4.z + w4.w * v4.w;
        }
        res[px * 54 + o] = acc + bsm[o];
    }
    __syncthreads();

    if (t < 72) {
        int px = t / 9, a = t - px * 9;
        int gp = gp0 + px;
        if (gp < 10000) {
            float imh = readScalar(pimh), imw = readScalar(pimw);
            const float* rr = res + px * 54;
            int n = gp / 2500, p = gp - n * 2500;
            int y = p / 50, x = p - y * 50;
            float s0 = rr[2 * a], s1 = rr[2 * a + 1];
            float d0 = rr[18 + 4 * a + 0], d1 = rr[18 + 4 * a + 1];
            float d2 = rr[18 + 4 * a + 2], d3 = rr[18 + 4 * a + 3];
            float yy = (float)(y * 16), xx = (float)(x * 16);
            float ay1 = yy + cAy1[a], ay2 = yy + cAy2[a];
            float ax1 = xx + cAx1[a], ax2 = xx + cAx2[a];
            float ah = ay2 - ay1, aw = ax2 - ax1;
            float acy = ay1 + 0.5f * ah, acx = ax1 + 0.5f * aw;
            float cy = d0 * ah + acy, cx = d1 * aw + acx;
            float bh = expf(d2) * ah, bw = expf(d3) * aw;
            float y1 = fminf(fmaxf(cy - 0.5f * bh, 0.f), imh);
            float y2 = fminf(fmaxf(cy + 0.5f * bh, 0.f), imh);
            float x1 = fminf(fmaxf(cx - 0.5f * bw, 0.f), imw);
            float x2 = fminf(fmaxf(cx + 0.5f * bw, 0.f), imw);
            bool valid = ((y2 - y1) >= 16.f) && ((x2 - x1) >= 16.f);
            float fg = 1.f / (1.f + expf(s0 - s1));
            int ridx = p * 9 + a;
            int gi = n * 22500 + ridx;
            out[OFF_LOC + (size_t)gi * 4 + 0] = d0;
            out[OFF_LOC + (size_t)gi * 4 + 1] = d1;
            out[OFF_LOC + (size_t)gi * 4 + 2] = d2;
            out[OFF_LOC + (size_t)gi * 4 + 3] = d3;
            out[OFF_SCORE + (size_t)gi * 2 + 0] = s0;
            out[OFF_SCORE + (size_t)gi * 2 + 1] = s1;
            float* bx = g_boxes + (size_t)gi * 4;
            bx[0] = y1; bx[1] = x1; bx[2] = y2; bx[3] = x2;
            float sc = valid ? fg : __int_as_float(0xff800000);
            g_keys[(size_t)n * NSORT + ridx] = packKey(sc, (unsigned)ridx);
        }
    }
}

// ================= anchors =================
__global__ void write_anchors(float* __restrict__ out) {
    int r = blockIdx.x * 256 + threadIdx.x;
    if (r < RTOT) {
        int a = r % 9; int pix = r / 9;
        int y = pix / 50, x = pix - y * 50;
        float yy = (float)(y * 16), xx = (float)(x * 16);
        out[OFF_ANC + (size_t)r * 4 + 0] = yy + cAy1[a];
        out[OFF_ANC + (size_t)r * 4 + 1] = xx + cAx1[a];
        out[OFF_ANC + (size_t)r * 4 + 2] = yy + cAy2[a];
        out[OFF_ANC + (size_t)r * 4 + 3] = xx + cAx2[a];
    }
}

// ================= bitonic sort =================
__global__ __launch_bounds__(1024)
void sort_local() {
    __shared__ unsigned long long s[4096];
    int chunk = blockIdx.x; int img = chunk >> 3; int cb = (chunk & 7) * 4096;
    unsigned long long* g = g_keys + (size_t)img * NSORT + cb;
    int t = threadIdx.x;
#pragma unroll
    for (int q = 0; q < 4; q++) s[t + q * 1024] = g[t + q * 1024];
    __syncthreads();
    for (int k = 2; k <= 4096; k <<= 1) {
        for (int j = k >> 1; j > 0; j >>= 1) {
#pragma unroll
            for (int q = 0; q < 2; q++) {
                int pid = t + q * 1024;
                int i = ((pid & ~(j - 1)) << 1) | (pid & (j - 1));
                int pr = i | j;
                bool asc = (((cb + i) & k) == 0);
                unsigned long long a = s[i], b = s[pr];
                if ((a > b) == asc) { s[i] = b; s[pr] = a; }
            }
            __syncthreads();
        }
    }
#pragma unroll
    for (int q = 0; q < 4; q++) g[t + q * 1024] = s[t + q * 1024];
}

__global__ void sort_gstep(int k, int j) {
    int t = blockIdx.x * blockDim.x + threadIdx.x;
    int n = t >> 14; int tt = t & 16383;
    int i = ((tt & ~(j - 1)) << 1) | (tt & (j - 1));
    bool asc = ((i & k) == 0);
    unsigned long long* g = g_keys + (size_t)n * NSORT;
    unsigned long long a = g[i], b = g[i | j];
    if ((a > b) == asc) { g[i] = b; g[i | j] = a; }
}

__global__ __launch_bounds__(1024)
void sort_lfinish(int k) {
    __shared__ unsigned long long s[4096];
    int chunk = blockIdx.x; int img = chunk >> 3; int cb = (chunk & 7) * 4096;
    unsigned long long* g = g_keys + (size_t)img * NSORT + cb;
    int t = threadIdx.x;
#pragma unroll
    for (int q = 0; q < 4; q++) s[t + q * 1024] = g[t + q * 1024];
    __syncthreads();
    bool asc = ((cb & k) == 0);
    for (int j = 2048; j > 0; j >>= 1) {
#pragma unroll
        for (int q = 0; q < 2; q++) {
            int pid = t + q * 1024;
            int i = ((pid & ~(j - 1)) << 1) | (pid & (j - 1));
            int pr = i | j;
            unsigned long long a = s[i], b = s[pr];
            if ((a > b) == asc) { s[i] = b; s[pr] = a; }
        }
        __syncthreads();
    }
#pragma unroll
    for (int q = 0; q < 4; q++) g[t + q * 1024] = s[t + q * 1024];
}

// ================= gather top-6000 =================
__global__ void gather_top() {
    int t = blockIdx.x * blockDim.x + threadIdx.x;
    if (t >= N_IMG * NBEF) return;
    int n = t / NBEF;
    unsigned long long key = g_keys[(size_t)n * NSORT + (t - n * NBEF)];
    unsigned idx = (unsigned)key;
    unsigned hi = (unsigned)(key >> 32);
    bool valid = hi < 0x80000000u;
    float4 b = make_float4(0, 0, 0, 0);
    if (idx < RTOT) b = *(const float4*)(g_boxes + ((size_t)n * RTOT + idx) * 4);
    *(float4*)(g_sboxes + (size_t)t * 4) = b;
    g_valid[t] = valid ? 1 : 0;
}

// ================= NMS bitmask =================
__global__ __launch_bounds__(64)
void nms_mask() {
    int cb = blockIdx.x, rb = blockIdx.y, n = blockIdx.z;
    int t = threadIdx.x;
    int i = rb * 64 + t;
    if (cb < rb) {
        if (i < NBEF) g_mask[((size_t)(n * NBEF) + i) * WORDS + cb] = 0ull;
        return;
    }
    __shared__ float4 cbox[64];
    int j0 = cb * 64;
    float4 b = make_float4(0, 0, 0, 0);
    if (j0 + t < NBEF) b = *(const float4*)(g_sboxes + ((size_t)n * NBEF + j0 + t) * 4);
    cbox[t] = b;
    __syncthreads();
    if (i >= NBEF) return;
    float4 r = *(const float4*)(g_sboxes + ((size_t)n * NBEF + i) * 4);
    float ra = (r.z - r.x) * (r.w - r.y);
    unsigned long long m = 0;
#pragma unroll 8
    for (int c = 0; c < 64; c++) {
        int j = j0 + c;
        float4 q = cbox[c];
        float ty = fmaxf(r.x, q.x), tx = fmaxf(r.y, q.y);
        float by = fminf(r.z, q.z), bx = fminf(r.w, q.w);
        float inter = fmaxf(by - ty, 0.f) * fmaxf(bx - tx, 0.f);
        float qa = (q.z - q.x) * (q.w - q.y);
        float iou = inter / (ra + qa - inter + 1e-9f);
        if (j > i && iou > 0.7f) m |= (1ull << c);
    }
    g_mask[((size_t)(n * NBEF) + i) * WORDS + cb] = m;
}

// ================= NMS serial scan =================
__global__ void nms_scan(float* __restrict__ out) {
    int n = blockIdx.x; int lane = threadIdx.x;
    unsigned long long rem[3] = {0, 0, 0};
    __shared__ int kl[NAFT];
    int kc = 0;
    for (int i = 0; i < NBEF && kc < NAFT; ++i) {
        int wi = i >> 6; int slot = wi >> 5; int owner = wi & 31;
        unsigned long long myw = (slot == 0) ? rem[0] : ((slot == 1) ? rem[1] : rem[2]);
        unsigned long long w = __shfl_sync(0xffffffffu, myw, owner);
        bool removed = (w >> (i & 63)) & 1ull;
        if (!removed && g_valid[(size_t)n * NBEF + i]) {
            if (lane == 0) kl[kc] = i;
            kc++;
            const unsigned long long* mr = g_mask + ((size_t)(n * NBEF) + i) * WORDS;
#pragma unroll
            for (int s = 0; s < 3; s++) {
                int ww = lane + 32 * s;
                if (ww < WORDS) rem[s] |= mr[ww];
            }
        }
    }
    __syncwarp();
    for (int r = lane; r < NAFT; r += 32) {
        float4 b = make_float4(0, 0, 0, 0);
        if (r < kc) b = *(const float4*)(g_sboxes + ((size_t)n * NBEF + kl[r]) * 4);
        float* dst = out + OFF_ROIS + (size_t)(n * NAFT + r) * 4;
        dst[0] = b.x; dst[1] = b.y; dst[2] = b.z; dst[3] = b.w;
        out[OFF_IDX + n * NAFT + r] = (float)n;
    }
}

// ================= launch =================
extern "C" void kernel_launch(void* const* d_in, const int* in_sizes, int n_in,
                              void* d_out, int out_size) {
    const float* x  = (const float*)d_in[0];
    const float* w1 = (const float*)d_in[1];
    const float* b1 = (const float*)d_in[2];
    const float* ws = (const float*)d_in[3];
    const float* bs = (const float*)d_in[4];
    const float* wl = (const float*)d_in[5];
    const float* bl = (const float*)d_in[6];
    const unsigned* ih = (const unsigned*)d_in[7];
    const unsigned* iw = (const unsigned*)d_in[8];
    float* out = (float*)d_out;

    cudaFuncSetAttribute(conv_mma, cudaFuncAttributeMaxDynamicSharedMemorySize, SMEM_CONV);
    cudaFuncSetAttribute(heads_kernel, cudaFuncAttributeMaxDynamicSharedMemorySize, SMEM_HEADS);

    wsplit<<<6912, 256>>>(w1);
    im2col_split<<<23040, 256>>>(x);
    fill_keys<<<512, 256>>>();
    conv_mma<<<dim3(4, 20, 4), 256, SMEM_CONV>>>(b1);
    heads_kernel<<<1250, 448, SMEM_HEADS>>>(ws, bs, wl, bl, out, ih, iw);
    write_anchors<<<88, 256>>>(out);

    sort_local<<<32, 1024>>>();
    sort_gstep<<<256, 256>>>(8192, 4096);
    sort_lfinish<<<32, 1024>>>(8192);
    sort_gstep<<<256, 256>>>(16384, 8192);
    sort_gstep<<<256, 256>>>(16384, 4096);
    sort_lfinish<<<32, 1024>>>(16384);
    sort_gstep<<<256, 256>>>(32768, 16384);
    sort_gstep<<<256, 256>>>(32768, 8192);
    sort_gstep<<<256, 256>>>(32768, 4096);
    sort_lfinish<<<32, 1024>>>(32768);

    gather_top<<<94, 256>>>();
    nms_mask<<<dim3(WORDS, WORDS, N_IMG), 64>>>();
    nms_scan<<<N_IMG, 32>>>(out);
}

// round 7
// speedup vs baseline: 1.4655x; 1.0015x over previous
#include <cuda_runtime.h>
#include <cuda_fp16.h>
#include <cstdint>
#include <math.h>

#define N_IMG 4
#define PXN   2500
#define NPAD  2560
#define RTOT  22500
#define NSORT 32768
#define NBEF  6000
#define NAFT  300
#define WORDS 94

#define OFF_LOC   0
#define OFF_SCORE 360000
#define OFF_ROIS  540000
#define OFF_IDX   544800
#define OFF_ANC   546000

#define KREAL 4608
#define KVIRT 27648
#define KCHUNK 64
#define NCHUNK 432
#define ASTG 16384
#define BSTG 16384
#define STGB (ASTG + BSTG)
#define SMEM_CONV (3 * STGB)          // 98304; also covers 128*129*4 transpose buf
#define SMEM_HEADS (32488*4)

#define SC1 2048.0f                   // 2^11
#define SC1I 4.8828125e-4f            // 2^-11
#define SC2 4194304.0f                // 2^22
#define SC2I 2.384185791015625e-7f    // 2^-22

// ---------------- scratch (static device memory; no allocs) ----------------
__device__ __align__(1024) __half g_aprime[(size_t)512 * KVIRT];
__device__ __align__(1024) __half g_bh[(size_t)N_IMG * NPAD * KREAL];
__device__ __align__(1024) __half g_bm[(size_t)N_IMG * NPAD * KREAL];
__device__ __align__(1024) __half g_bl[(size_t)N_IMG * NPAD * KREAL];
__device__ float              g_inter[(size_t)N_IMG * PXN * 512];
__device__ float              g_boxes[(size_t)N_IMG * RTOT * 4];
__device__ unsigned long long g_keys [(size_t)N_IMG * NSORT];
__device__ float              g_sboxes[(size_t)N_IMG * NBEF * 4];
__device__ unsigned char      g_valid [(size_t)N_IMG * NBEF];
__device__ unsigned long long g_mask [(size_t)N_IMG * NBEF * WORDS];

__constant__ float cAy1[9] = {-37.254833991878082f, -82.509667991878075f, -173.01933598375615f,
                              -56.0f, -120.0f, -248.0f,
                              -82.509667991878075f, -173.01933598375615f, -354.03867196751231f};
__constant__ float cAy2[9] = { 53.254833991878082f,  98.509667991878075f,  189.01933598375615f,
                               72.0f,  136.0f,  264.0f,
                               98.509667991878075f,  189.01933598375615f,  370.03867196751231f};
__constant__ float cAx1[9] = {-82.509667991878075f, -173.01933598375615f, -354.03867196751231f,
                              -56.0f, -120.0f, -248.0f,
                              -37.254833991878082f, -82.509667991878075f, -173.01933598375615f};
__constant__ float cAx2[9] = { 98.509667991878075f,  189.01933598375615f,  370.03867196751231f,
                               72.0f,  136.0f,  264.0f,
                               53.254833991878082f,  98.509667991878075f,  189.01933598375615f};

// ---------------- helpers ----------------
__device__ __forceinline__ uint32_t smem_u32(const void* p) {
    uint32_t a;
    asm("{ .reg .u64 t; cvta.to.shared.u64 t, %1; cvt.u32.u64 %0, t; }" : "=r"(a) : "l"(p));
    return a;
}
__device__ __forceinline__ void cpa16(uint32_t d, const void* s) {
    asm volatile("cp.async.cg.shared.global [%0], [%1], 16;" :: "r"(d), "l"(s) : "memory");
}
#define LDSM_X4(r, addr) \
    asm volatile("ldmatrix.sync.aligned.m8n8.x4.shared.b16 {%0,%1,%2,%3}, [%4];" \
        : "=r"((r)[0]), "=r"((r)[1]), "=r"((r)[2]), "=r"((r)[3]) : "r"(addr))
__device__ __forceinline__ void mma16816(float* c, const uint32_t* a, const uint32_t* b) {
    asm volatile("mma.sync.aligned.m16n8k16.row.col.f32.f16.f16.f32 "
        "{%0,%1,%2,%3}, {%4,%5,%6,%7}, {%8,%9}, {%0,%1,%2,%3};"
        : "+f"(c[0]), "+f"(c[1]), "+f"(c[2]), "+f"(c[3])
        : "r"(a[0]), "r"(a[1]), "r"(a[2]), "r"(a[3]), "r"(b[0]), "r"(b[1]));
}
// d = a*b + 0   (fresh accumulator per chunk)
__device__ __forceinline__ void mma16816_z(float* d, const uint32_t* a, const uint32_t* b) {
    asm volatile("mma.sync.aligned.m16n8k16.row.col.f32.f16.f16.f32 "
        "{%0,%1,%2,%3}, {%4,%5,%6,%7}, {%8,%9}, {%10,%11,%12,%13};"
        : "=f"(d[0]), "=f"(d[1]), "=f"(d[2]), "=f"(d[3])
        : "r"(a[0]), "r"(a[1]), "r"(a[2]), "r"(a[3]), "r"(b[0]), "r"(b[1]),
          "f"(0.f), "f"(0.f), "f"(0.f), "f"(0.f));
}

__device__ __forceinline__ unsigned long long packKey(float s, unsigned idx) {
    unsigned b = __float_as_uint(s);
    unsigned m = b ^ ((b & 0x80000000u) ? 0xFFFFFFFFu : 0x80000000u);
    return ((unsigned long long)(~m) << 32) | (unsigned long long)idx;
}
__device__ __forceinline__ float readScalar(const unsigned* p) {
    unsigned u = *p;
    return (u < 0x10000u) ? (float)u : __uint_as_float(u);
}

// 3-way scaled split: v = h + 2^-11 m + 2^-22 l, all parts fp16-normal range
__device__ __forceinline__ void split3(float v, __half& h, __half& m, __half& l) {
    h = __float2half_rn(v);
    float r1 = v - __half2float(h);
    m = __float2half_rn(r1 * SC1);
    float r2 = r1 - __half2float(m) * SC1I;
    l = __float2half_rn(r2 * SC2);
}

// ================= weight split: A' = [h|h|h|m|m|l] blocks, 512 x 27648 fp16 =================
__global__ void wsplit(const float* __restrict__ W) {
    int idx = blockIdx.x * 256 + threadIdx.x;           // 512*3456 = 1769472
    if (idx >= 512 * (KVIRT / 8)) return;
    int m = idx / (KVIRT / 8), kg = idx - m * (KVIRT / 8);
    int kp = kg * 8;
    int blk = kp / KREAL;
    int k = kp - blk * KREAL;
    const float* src = W + (size_t)m * KREAL + k;
    __half o[8];
#pragma unroll
    for (int e = 0; e < 8; e++) {
        __half h, mm, l;
        split3(src[e], h, mm, l);
        o[e] = (blk < 3) ? h : ((blk < 5) ? mm : l);
    }
    *(uint4*)(g_aprime + (size_t)m * KVIRT + kp) = *(uint4*)o;
}

// ================= im2col + 3-way split =================
__global__ void im2col_split(const float* __restrict__ X) {
    int idx = blockIdx.x * 256 + threadIdx.x;
    if (idx >= N_IMG * NPAD * (KREAL / 8)) return;
    int kg = idx % (KREAL / 8);
    int rest = idx / (KREAL / 8);
    int p = rest % NPAD;
    int img = rest / NPAD;
    __half hb[8], mb[8], lb[8];
    if (p < PXN) {
        int y = p / 50, x = p - y * 50;
#pragma unroll
        for (int e = 0; e < 8; e++) {
            int k = kg * 8 + e;
            int c = k / 9; int r9 = k - c * 9; int ky = r9 / 3; int kx = r9 - ky * 3;
            int sy = y + ky - 1, sx = x + kx - 1;
            float v = 0.f;
            if ((unsigned)sy < 50u && (unsigned)sx < 50u)
                v = X[((size_t)(img * 512 + c)) * 2500 + sy * 50 + sx];
            split3(v, hb[e], mb[e], lb[e]);
        }
    } else {
#pragma unroll
        for (int e = 0; e < 8; e++) {
            hb[e] = __ushort_as_half(0); mb[e] = __ushort_as_half(0); lb[e] = __ushort_as_half(0);
        }
    }
    size_t base = ((size_t)img * NPAD + p) * KREAL + kg * 8;
    *(uint4*)(g_bh + base) = *(uint4*)hb;
    *(uint4*)(g_bm + base) = *(uint4*)mb;
    *(uint4*)(g_bl + base) = *(uint4*)lb;
}

// ================= HMMA conv GEMM: 6-product scaled split, K=27648 =================
// grid (4 m-tiles, 20 n-tiles, 4 img), 256 threads (8 warps, 2x4 warp grid)
__global__ void __launch_bounds__(256, 2) conv_mma(const float* __restrict__ bias) {
    extern __shared__ char dsm[];
    __shared__ float sbias[128];
    const int tid = threadIdx.x;
    const int wid = tid >> 5, lane = tid & 31;
    const int bm = blockIdx.x, bn = blockIdx.y, img = blockIdx.z;
    const int warp_m = wid >> 2, warp_n = wid & 3;
    const uint32_t base = smem_u32(dsm);

    if (tid < 128) sbias[tid] = bias[bm * 128 + tid];

    const __half* gA = g_aprime + (size_t)(bm * 128) * KVIRT;
    const size_t brow = ((size_t)img * NPAD + bn * 128) * KREAL;

    float acc[4][4][4];
#pragma unroll
    for (int i = 0; i < 4; i++)
#pragma unroll
        for (int j = 0; j < 4; j++)
#pragma unroll
            for (int e = 0; e < 4; e++) acc[i][j][e] = 0.f;

    const int lr = tid >> 3, lc = tid & 7;
    const int lcs = ((lc ^ (lr & 7)) * 16);

    const int ra = warp_m * 64 + (lane & 15);
    const int kha = (lane >> 4);
    const int xa = ra & 7;
    const int q8 = lane >> 3;
    const int xb = lane & 7;

#define LOAD_STAGE(T, S) do { \
    uint32_t sa_ = base + (S) * STGB; \
    int k0_ = (T) * KCHUNK; \
    const __half* gAr_ = gA + k0_ + lc * 8; \
    _Pragma("unroll") \
    for (int i_ = 0; i_ < 4; i_++) { \
        int r_ = lr + 32 * i_; \
        cpa16(sa_ + r_ * 128 + lcs, gAr_ + (size_t)r_ * KVIRT); \
    } \
    int blk_ = (T) / 72; \
    int kr_ = ((T) - blk_ * 72) * KCHUNK; \
    const __half* gBsel_ = (blk_ == 2) ? g_bl : ((blk_ == 1 || blk_ == 4) ? g_bm : g_bh); \
    const __half* gBr_ = gBsel_ + brow + kr_ + lc * 8; \
    uint32_t sb_ = sa_ + ASTG; \
    _Pragma("unroll") \
    for (int i_ = 0; i_ < 4; i_++) { \
        int r_ = lr + 32 * i_; \
        cpa16(sb_ + r_ * 128 + lcs, gBr_ + (size_t)r_ * KREAL); \
    } \
    asm volatile("cp.async.commit_group;" ::: "memory"); \
} while (0)

    LOAD_STAGE(0, 0);
    LOAD_STAGE(1, 1);

    int sCmp = 0, sLoad = 2;
    for (int t = 0; t < NCHUNK; t++) {
        if (t < NCHUNK - 2) asm volatile("cp.async.wait_group 1;" ::: "memory");
        else                asm volatile("cp.async.wait_group 0;" ::: "memory");
        __syncthreads();

        int blkc = t / 72;
        float cscale = (blkc == 0) ? 1.f
                     : ((blkc == 1 || blkc == 3) ? SC1I : SC2I);

        uint32_t sa = base + sCmp * STGB;
        uint32_t sb = sa + ASTG;
#pragma unroll
        for (int mt = 0; mt < 4; mt++) {
            uint32_t a[4][4];
            const int rA = ra + mt * 16;
#pragma unroll
            for (int kk = 0; kk < 4; kk++)
                LDSM_X4(a[kk], sa + rA * 128 + (((kk * 2 + kha) ^ xa) * 16));
#pragma unroll
            for (int nt = 0; nt < 4; nt++) {
                const int rB = warp_n * 32 + nt * 8 + xb;
                uint32_t b[8];
                LDSM_X4(b,     sb + rB * 128 + (((0 + q8) ^ xb) * 16));
                LDSM_X4(b + 4, sb + rB * 128 + (((4 + q8) ^ xb) * 16));
                float tmp[4];
                mma16816_z(tmp, a[0], b);
                mma16816(tmp, a[1], b + 2);
                mma16816(tmp, a[2], b + 4);
                mma16816(tmp, a[3], b + 6);
#pragma unroll
                for (int e = 0; e < 4; e++)
                    acc[mt][nt][e] = fmaf(tmp[e], cscale, acc[mt][nt][e]);
            }
        }

        if (t + 2 < NCHUNK) LOAD_STAGE(t + 2, sLoad);
        if (++sLoad == 3) sLoad = 0;
        if (++sCmp == 3) sCmp = 0;
    }

    // epilogue: transpose through smem (stride 129), bias + relu, coalesced store
    __syncthreads();
    float* tb = (float*)dsm;
#pragma unroll
    for (int mt = 0; mt < 4; mt++)
#pragma unroll
        for (int nt = 0; nt < 4; nt++) {
            int m = warp_m * 64 + mt * 16 + (lane >> 2);
            int n = warp_n * 32 + nt * 8 + 2 * (lane & 3);
            tb[m * 129 + n]           = acc[mt][nt][0];
            tb[m * 129 + n + 1]       = acc[mt][nt][1];
            tb[(m + 8) * 129 + n]     = acc[mt][nt][2];
            tb[(m + 8) * 129 + n + 1] = acc[mt][nt][3];
        }
    __syncthreads();

    const int j = tid >> 1, half = tid & 1;
    const int p = bn * 128 + j;
    if (p < PXN) {
        float* dst = g_inter + ((size_t)(img * PXN + p)) * 512 + bm * 128 + half * 64;
#pragma unroll
        for (int i = 0; i < 16; i++) {
            int m0 = half * 64 + i * 4;
            float4 v;
            v.x = fmaxf(tb[(m0 + 0) * 129 + j] + sbias[m0 + 0], 0.f);
            v.y = fmaxf(tb[(m0 + 1) * 129 + j] + sbias[m0 + 1], 0.f);
            v.z = fmaxf(tb[(m0 + 2) * 129 + j] + sbias[m0 + 2], 0.f);
            v.w = fmaxf(tb[(m0 + 3) * 129 + j] + sbias[m0 + 3], 0.f);
            *(float4*)(dst + i * 4) = v;
        }
    }
#undef LOAD_STAGE
}

// ================= key padding =================
__global__ void fill_keys() {
    int t = blockIdx.x * blockDim.x + threadIdx.x;
    if (t < N_IMG * NSORT) g_keys[t] = ~0ull;
}

// ================= heads =================
__global__ __launch_bounds__(448)
void heads_kernel(const float* __restrict__ WS, const float* __restrict__ BS,
                  const float* __restrict__ WL, const float* __restrict__ BL,
                  float* __restrict__ out,
                  const unsigned* __restrict__ pimh, const unsigned* __restrict__ pimw) {
    extern __shared__ float sm[];
    float* wsm = sm;            // 54 rows, stride 516
    float* vsm = sm + 27864;    // 8 rows, stride 516
    float* bsm = sm + 31992;
    float* res = sm + 32056;
    const int t = threadIdx.x;
    const int gp0 = blockIdx.x * 8;

    for (int i = t; i < 18 * 512; i += 448) { int r = i >> 9, c = i & 511; wsm[r * 516 + c] = WS[i]; }
    for (int i = t; i < 36 * 512; i += 448) { int r = i >> 9, c = i & 511; wsm[(18 + r) * 516 + c] = WL[i]; }
    if (t < 18) bsm[t] = BS[t]; else if (t < 54) bsm[t] = BL[t - 18];
    for (int i = t; i < 8 * 512; i += 448) {
        int p = i >> 9, c = i & 511;
        int gp = gp0 + p;
        vsm[p * 516 + c] = (gp < 10000) ? g_inter[(size_t)gp * 512 + c] : 0.f;
    }
    __syncthreads();

    if (t < 432) {
        int o = t >> 3, px = t & 7;
        const float4* wv = (const float4*)(wsm + o * 516);
        const float4* vv = (const float4*)(vsm + px * 516);
        float acc = 0.f;
#pragma unroll 8
        for (int q = 0; q < 128; q++) {
            float4 w4 = wv[q], v4 = vv[q];
            acc += w4.x * v4.x + w4.y * v4.y + w4.z * v4.z + w4.w * v4.w;
        }
        res[px * 54 + o] = acc + bsm[o];
    }
    __syncthreads();

    if (t < 72) {
        int px = t / 9, a = t - px * 9;
        int gp = gp0 + px;
        if (gp < 10000) {
            float imh = readScalar(pimh), imw = readScalar(pimw);
            const float* rr = res + px * 54;
            int n = gp / 2500, p = gp - n * 2500;
            int y = p / 50, x = p - y * 50;
            float s0 = rr[2 * a], s1 = rr[2 * a + 1];
            float d0 = rr[18 + 4 * a + 0], d1 = rr[18 + 4 * a + 1];
            float d2 = rr[18 + 4 * a + 2], d3 = rr[18 + 4 * a + 3];
            float yy = (float)(y * 16), xx = (float)(x * 16);
            float ay1 = yy + cAy1[a], ay2 = yy + cAy2[a];
            float ax1 = xx + cAx1[a], ax2 = xx + cAx2[a];
            float ah = ay2 - ay1, aw = ax2 - ax1;
            float acy = ay1 + 0.5f * ah, acx = ax1 + 0.5f * aw;
            float cy = d0 * ah + acy, cx = d1 * aw + acx;
            float bh = expf(d2) * ah, bw = expf(d3) * aw;
            float y1 = fminf(fmaxf(cy - 0.5f * bh, 0.f), imh);
            float y2 = fminf(fmaxf(cy + 0.5f * bh, 0.f), imh);
            float x1 = fminf(fmaxf(cx - 0.5f * bw, 0.f), imw);
            float x2 = fminf(fmaxf(cx + 0.5f * bw, 0.f), imw);
            bool valid = ((y2 - y1) >= 16.f) && ((x2 - x1) >= 16.f);
            float fg = 1.f / (1.f + expf(s0 - s1));
            int ridx = p * 9 + a;
            int gi = n * 22500 + ridx;
            out[OFF_LOC + (size_t)gi * 4 + 0] = d0;
            out[OFF_LOC + (size_t)gi * 4 + 1] = d1;
            out[OFF_LOC + (size_t)gi * 4 + 2] = d2;
            out[OFF_LOC + (size_t)gi * 4 + 3] = d3;
            out[OFF_SCORE + (size_t)gi * 2 + 0] = s0;
            out[OFF_SCORE + (size_t)gi * 2 + 1] = s1;
            float* bx = g_boxes + (size_t)gi * 4;
            bx[0] = y1; bx[1] = x1; bx[2] = y2; bx[3] = x2;
            float sc = valid ? fg : __int_as_float(0xff800000);
            g_keys[(size_t)n * NSORT + ridx] = packKey(sc, (unsigned)ridx);
        }
    }
}

// ================= anchors =================
__global__ void write_anchors(float* __restrict__ out) {
    int r = blockIdx.x * 256 + threadIdx.x;
    if (r < RTOT) {
        int a = r % 9; int pix = r / 9;
        int y = pix / 50, x = pix - y * 50;
        float yy = (float)(y * 16), xx = (float)(x * 16);
        out[OFF_ANC + (size_t)r * 4 + 0] = yy + cAy1[a];
        out[OFF_ANC + (size_t)r * 4 + 1] = xx + cAx1[a];
        out[OFF_ANC + (size_t)r * 4 + 2] = yy + cAy2[a];
        out[OFF_ANC + (size_t)r * 4 + 3] = xx + cAx2[a];
    }
}

// ================= bitonic sort =================
__global__ __launch_bounds__(1024)
void sort_local() {
    __shared__ unsigned long long s[4096];
    int chunk = blockIdx.x; int img = chunk >> 3; int cb = (chunk & 7) * 4096;
    unsigned long long* g = g_keys + (size_t)img * NSORT + cb;
    int t = threadIdx.x;
#pragma unroll
    for (int q = 0; q < 4; q++) s[t + q * 1024] = g[t + q * 1024];
    __syncthreads();
    for (int k = 2; k <= 4096; k <<= 1) {
        for (int j = k >> 1; j > 0; j >>= 1) {
#pragma unroll
            for (int q = 0; q < 2; q++) {
                int pid = t + q * 1024;
                int i = ((pid & ~(j - 1)) << 1) | (pid & (j - 1));
                int pr = i | j;
                bool asc = (((cb + i) & k) == 0);
                unsigned long long a = s[i], b = s[pr];
                if ((a > b) == asc) { s[i] = b; s[pr] = a; }
            }
            __syncthreads();
        }
    }
#pragma unroll
    for (int q = 0; q < 4; q++) g[t + q * 1024] = s[t + q * 1024];
}

__global__ void sort_gstep(int k, int j) {
    int t = blockIdx.x * blockDim.x + threadIdx.x;
    int n = t >> 14; int tt = t & 16383;
    int i = ((tt & ~(j - 1)) << 1) | (tt & (j - 1));
    bool asc = ((i & k) == 0);
    unsigned long long* g = g_keys + (size_t)n * NSORT;
    unsigned long long a = g[i], b = g[i | j];
    if ((a > b) == asc) { g[i] = b; g[i | j] = a; }
}

__global__ __launch_bounds__(1024)
void sort_lfinish(int k) {
    __shared__ unsigned long long s[4096];
    int chunk = blockIdx.x; int img = chunk >> 3; int cb = (chunk & 7) * 4096;
    unsigned long long* g = g_keys + (size_t)img * NSORT + cb;
    int t = threadIdx.x;
#pragma unroll
    for (int q = 0; q < 4; q++) s[t + q * 1024] = g[t + q * 1024];
    __syncthreads();
    bool asc = ((cb & k) == 0);
    for (int j = 2048; j > 0; j >>= 1) {
#pragma unroll
        for (int q = 0; q < 2; q++) {
            int pid = t + q * 1024;
            int i = ((pid & ~(j - 1)) << 1) | (pid & (j - 1));
            int pr = i | j;
            unsigned long long a = s[i], b = s[pr];
            if ((a > b) == asc) { s[i] = b; s[pr] = a; }
        }
        __syncthreads();
    }
#pragma unroll
    for (int q = 0; q < 4; q++) g[t + q * 1024] = s[t + q * 1024];
}

// ================= gather top-6000 =================
__global__ void gather_top() {
    int t = blockIdx.x * blockDim.x + threadIdx.x;
    if (t >= N_IMG * NBEF) return;
    int n = t / NBEF;
    unsigned long long key = g_keys[(size_t)n * NSORT + (t - n * NBEF)];
    unsigned idx = (unsigned)key;
    unsigned hi = (unsigned)(key >> 32);
    bool valid = hi < 0x80000000u;
    float4 b = make_float4(0, 0, 0, 0);
    if (idx < RTOT) b = *(const float4*)(g_boxes + ((size_t)n * RTOT + idx) * 4);
    *(float4*)(g_sboxes + (size_t)t * 4) = b;
    g_valid[t] = valid ? 1 : 0;
}

// ================= NMS bitmask =================
__global__ __launch_bounds__(64)
void nms_mask() {
    int cb = blockIdx.x, rb = blockIdx.y, n = blockIdx.z;
    int t = threadIdx.x;
    int i = rb * 64 + t;
    if (cb < rb) {
        if (i < NBEF) g_mask[((size_t)(n * NBEF) + i) * WORDS + cb] = 0ull;
        return;
    }
    __shared__ float4 cbox[64];
    int j0 = cb * 64;
    float4 b = make_float4(0, 0, 0, 0);
    if (j0 + t < NBEF) b = *(const float4*)(g_sboxes + ((size_t)n * NBEF + j0 + t) * 4);
    cbox[t] = b;
    __syncthreads();
    if (i >= NBEF) return;
    float4 r = *(const float4*)(g_sboxes + ((size_t)n * NBEF + i) * 4);
    float ra = (r.z - r.x) * (r.w - r.y);
    unsigned long long m = 0;
#pragma unroll 8
    for (int c = 0; c < 64; c++) {
        int j = j0 + c;
        float4 q = cbox[c];
        float ty = fmaxf(r.x, q.x), tx = fmaxf(r.y, q.y);
        float by = fminf(r.z, q.z), bx = fminf(r.w, q.w);
        float inter = fmaxf(by - ty, 0.f) * fmaxf(bx - tx, 0.f);
        float qa = (q.z - q.x) * (q.w - q.y);
        float iou = inter / (ra + qa - inter + 1e-9f);
        if (j > i && iou > 0.7f) m |= (1ull << c);
    }
    g_mask[((size_t)(n * NBEF) + i) * WORDS + cb] = m;
}

// ================= NMS serial scan =================
__global__ void nms_scan(float* __restrict__ out) {
    int n = blockIdx.x; int lane = threadIdx.x;
    unsigned long long rem[3] = {0, 0, 0};
    __shared__ int kl[NAFT];
    int kc = 0;
    for (int i = 0; i < NBEF && kc < NAFT; ++i) {
        int wi = i >> 6; int slot = wi >> 5; int owner = wi & 31;
        unsigned long long myw = (slot == 0) ? rem[0] : ((slot == 1) ? rem[1] : rem[2]);
        unsigned long long w = __shfl_sync(0xffffffffu, myw, owner);
        bool removed = (w >> (i & 63)) & 1ull;
        if (!removed && g_valid[(size_t)n * NBEF + i]) {
            if (lane == 0) kl[kc] = i;
            kc++;
            const unsigned long long* mr = g_mask + ((size_t)(n * NBEF) + i) * WORDS;
#pragma unroll
            for (int s = 0; s < 3; s++) {
                int ww = lane + 32 * s;
                if (ww < WORDS) rem[s] |= mr[ww];
            }
        }
    }
    __syncwarp();
    for (int r = lane; r < NAFT; r += 32) {
        float4 b = make_float4(0, 0, 0, 0);
        if (r < kc) b = *(const float4*)(g_sboxes + ((size_t)n * NBEF + kl[r]) * 4);
        float* dst = out + OFF_ROIS + (size_t)(n * NAFT + r) * 4;
        dst[0] = b.x; dst[1] = b.y; dst[2] = b.z; dst[3] = b.w;
        out[OFF_IDX + n * NAFT + r] = (float)n;
    }
}

// ================= launch =================
extern "C" void kernel_launch(void* const* d_in, const int* in_sizes, int n_in,
                              void* d_out, int out_size) {
    const float* x  = (const float*)d_in[0];
    const float* w1 = (const float*)d_in[1];
    const float* b1 = (const float*)d_in[2];
    const float* ws = (const float*)d_in[3];
    const float* bs = (const float*)d_in[4];
    const float* wl = (const float*)d_in[5];
    const float* bl = (const float*)d_in[6];
    const unsigned* ih = (const unsigned*)d_in[7];
    const unsigned* iw = (const unsigned*)d_in[8];
    float* out = (float*)d_out;

    cudaFuncSetAttribute(conv_mma, cudaFuncAttributeMaxDynamicSharedMemorySize, SMEM_CONV);
    cudaFuncSetAttribute(heads_kernel, cudaFuncAttributeMaxDynamicSharedMemorySize, SMEM_HEADS);

    wsplit<<<6912, 256>>>(w1);
    im2col_split<<<23040, 256>>>(x);
    fill_keys<<<512, 256>>>();
    conv_mma<<<dim3(4, 20, 4), 256, SMEM_CONV>>>(b1);
    heads_kernel<<<1250, 448, SMEM_HEADS>>>(ws, bs, wl, bl, out, ih, iw);
    write_anchors<<<88, 256>>>(out);

    sort_local<<<32, 1024>>>();
    sort_gstep<<<256, 256>>>(8192, 4096);
    sort_lfinish<<<32, 1024>>>(8192);
    sort_gstep<<<256, 256>>>(16384, 8192);
    sort_gstep<<<256, 256>>>(16384, 4096);
    sort_lfinish<<<32, 1024>>>(16384);
    sort_gstep<<<256, 256>>>(32768, 16384);
    sort_gstep<<<256, 256>>>(32768, 8192);
    sort_gstep<<<256, 256>>>(32768, 4096);
    sort_lfinish<<<32, 1024>>>(32768);

    gather_top<<<94, 256>>>();
    nms_mask<<<dim3(WORDS, WORDS, N_IMG), 64>>>();
    nms_scan<<<N_IMG, 32>>>(out);
}

// round 8
// speedup vs baseline: 1.4671x; 1.0011x over previous
#include <cuda_runtime.h>
#include <cuda_fp16.h>
#include <cstdint>
#include <math.h>

#define N_IMG 4
#define PXN   2500
#define NPAD  2560
#define RTOT  22500
#define NSORT 32768
#define NBEF  6000
#define NAFT  300
#define WORDS 94

#define OFF_LOC   0
#define OFF_SCORE 360000
#define OFF_ROIS  540000
#define OFF_IDX   544800
#define OFF_ANC   546000

#define KREAL 4608
#define KVIRT 27648
#define KCHUNK 64
#define NCHUNK 432
#define ASTG 16384
#define BSTG 16384
#define STGB (ASTG + BSTG)
#define SMEM_CONV (3 * STGB)          // 98304; also covers 128*129*4 transpose buf
#define SMEM_HEADS (32488*4)

#define SC1 2048.0f                   // 2^11
#define SC1I 4.8828125e-4f            // 2^-11
#define SC2 4194304.0f                // 2^22
#define SC2I 2.384185791015625e-7f    // 2^-22

// ---------------- scratch (static device memory; no allocs) ----------------
__device__ __align__(1024) __half g_aprime[(size_t)512 * KVIRT];
__device__ __align__(1024) __half g_bh[(size_t)N_IMG * NPAD * KREAL];
__device__ __align__(1024) __half g_bm[(size_t)N_IMG * NPAD * KREAL];
__device__ __align__(1024) __half g_bl[(size_t)N_IMG * NPAD * KREAL];
__device__ float              g_inter[(size_t)N_IMG * PXN * 512];
__device__ float              g_boxes[(size_t)N_IMG * RTOT * 4];
__device__ unsigned long long g_keys [(size_t)N_IMG * NSORT];
__device__ float              g_sboxes[(size_t)N_IMG * NBEF * 4];
__device__ unsigned char      g_valid [(size_t)N_IMG * NBEF];
__device__ unsigned long long g_mask [(size_t)N_IMG * NBEF * WORDS];

__constant__ float cAy1[9] = {-37.254833991878082f, -82.509667991878075f, -173.01933598375615f,
                              -56.0f, -120.0f, -248.0f,
                              -82.509667991878075f, -173.01933598375615f, -354.03867196751231f};
__constant__ float cAy2[9] = { 53.254833991878082f,  98.509667991878075f,  189.01933598375615f,
                               72.0f,  136.0f,  264.0f,
                               98.509667991878075f,  189.01933598375615f,  370.03867196751231f};
__constant__ float cAx1[9] = {-82.509667991878075f, -173.01933598375615f, -354.03867196751231f,
                              -56.0f, -120.0f, -248.0f,
                              -37.254833991878082f, -82.509667991878075f, -173.01933598375615f};
__constant__ float cAx2[9] = { 98.509667991878075f,  189.01933598375615f,  370.03867196751231f,
                               72.0f,  136.0f,  264.0f,
                               53.254833991878082f,  98.509667991878075f,  189.01933598375615f};

// ---------------- helpers ----------------
__device__ __forceinline__ uint32_t smem_u32(const void* p) {
    uint32_t a;
    asm("{ .reg .u64 t; cvta.to.shared.u64 t, %1; cvt.u32.u64 %0, t; }" : "=r"(a) : "l"(p));
    return a;
}
__device__ __forceinline__ void cpa16(uint32_t d, const void* s) {
    asm volatile("cp.async.cg.shared.global [%0], [%1], 16;" :: "r"(d), "l"(s) : "memory");
}
#define LDSM_X4(r, addr) \
    asm volatile("ldmatrix.sync.aligned.m8n8.x4.shared.b16 {%0,%1,%2,%3}, [%4];" \
        : "=r"((r)[0]), "=r"((r)[1]), "=r"((r)[2]), "=r"((r)[3]) : "r"(addr))
__device__ __forceinline__ void mma16816(float* c, const uint32_t* a, const uint32_t* b) {
    asm volatile("mma.sync.aligned.m16n8k16.row.col.f32.f16.f16.f32 "
        "{%0,%1,%2,%3}, {%4,%5,%6,%7}, {%8,%9}, {%0,%1,%2,%3};"
        : "+f"(c[0]), "+f"(c[1]), "+f"(c[2]), "+f"(c[3])
        : "r"(a[0]), "r"(a[1]), "r"(a[2]), "r"(a[3]), "r"(b[0]), "r"(b[1]));
}
// d = a*b + 0   (fresh accumulator per chunk)
__device__ __forceinline__ void mma16816_z(float* d, const uint32_t* a, const uint32_t* b) {
    asm volatile("mma.sync.aligned.m16n8k16.row.col.f32.f16.f16.f32 "
        "{%0,%1,%2,%3}, {%4,%5,%6,%7}, {%8,%9}, {%10,%11,%12,%13};"
        : "=f"(d[0]), "=f"(d[1]), "=f"(d[2]), "=f"(d[3])
        : "r"(a[0]), "r"(a[1]), "r"(a[2]), "r"(a[3]), "r"(b[0]), "r"(b[1]),
          "f"(0.f), "f"(0.f), "f"(0.f), "f"(0.f));
}

__device__ __forceinline__ unsigned long long packKey(float s, unsigned idx) {
    unsigned b = __float_as_uint(s);
    unsigned m = b ^ ((b & 0x80000000u) ? 0xFFFFFFFFu : 0x80000000u);
    return ((unsigned long long)(~m) << 32) | (unsigned long long)idx;
}
__device__ __forceinline__ float readScalar(const unsigned* p) {
    unsigned u = *p;
    return (u < 0x10000u) ? (float)u : __uint_as_float(u);
}

// 3-way scaled split: v = h + 2^-11 m + 2^-22 l, all parts fp16-normal range
__device__ __forceinline__ void split3(float v, __half& h, __half& m, __half& l) {
    h = __float2half_rn(v);
    float r1 = v - __half2float(h);
    m = __float2half_rn(r1 * SC1);
    float r2 = r1 - __half2float(m) * SC1I;
    l = __float2half_rn(r2 * SC2);
}

// ================= weight split: A' = [h|h|h|m|m|l] blocks, 512 x 27648 fp16 =================
__global__ void wsplit(const float* __restrict__ W) {
    int idx = blockIdx.x * 256 + threadIdx.x;           // 512*3456 = 1769472
    if (idx >= 512 * (KVIRT / 8)) return;
    int m = idx / (KVIRT / 8), kg = idx - m * (KVIRT / 8);
    int kp = kg * 8;
    int blk = kp / KREAL;
    int k = kp - blk * KREAL;
    const float* src = W + (size_t)m * KREAL + k;
    __half o[8];
#pragma unroll
    for (int e = 0; e < 8; e++) {
        __half h, mm, l;
        split3(src[e], h, mm, l);
        o[e] = (blk < 3) ? h : ((blk < 5) ? mm : l);
    }
    *(uint4*)(g_aprime + (size_t)m * KVIRT + kp) = *(uint4*)o;
}

// ================= im2col + 3-way split =================
__global__ void im2col_split(const float* __restrict__ X) {
    int idx = blockIdx.x * 256 + threadIdx.x;
    if (idx >= N_IMG * NPAD * (KREAL / 8)) return;
    int kg = idx % (KREAL / 8);
    int rest = idx / (KREAL / 8);
    int p = rest % NPAD;
    int img = rest / NPAD;
    __half hb[8], mb[8], lb[8];
    if (p < PXN) {
        int y = p / 50, x = p - y * 50;
#pragma unroll
        for (int e = 0; e < 8; e++) {
            int k = kg * 8 + e;
            int c = k / 9; int r9 = k - c * 9; int ky = r9 / 3; int kx = r9 - ky * 3;
            int sy = y + ky - 1, sx = x + kx - 1;
            float v = 0.f;
            if ((unsigned)sy < 50u && (unsigned)sx < 50u)
                v = X[((size_t)(img * 512 + c)) * 2500 + sy * 50 + sx];
            split3(v, hb[e], mb[e], lb[e]);
        }
    } else {
#pragma unroll
        for (int e = 0; e < 8; e++) {
            hb[e] = __ushort_as_half(0); mb[e] = __ushort_as_half(0); lb[e] = __ushort_as_half(0);
        }
    }
    size_t base = ((size_t)img * NPAD + p) * KREAL + kg * 8;
    *(uint4*)(g_bh + base) = *(uint4*)hb;
    *(uint4*)(g_bm + base) = *(uint4*)mb;
    *(uint4*)(g_bl + base) = *(uint4*)lb;
}

// ================= HMMA conv GEMM: 6-product scaled split, K=27648 =================
// grid (4 m-tiles, 20 n-tiles, 4 img), 256 threads (8 warps, 2x4 warp grid)
__global__ void __launch_bounds__(256, 2) conv_mma(const float* __restrict__ bias) {
    extern __shared__ char dsm[];
    __shared__ float sbias[128];
    const int tid = threadIdx.x;
    const int wid = tid >> 5, lane = tid & 31;
    const int bm = blockIdx.x, bn = blockIdx.y, img = blockIdx.z;
    const int warp_m = wid >> 2, warp_n = wid & 3;
    const uint32_t base = smem_u32(dsm);

    if (tid < 128) sbias[tid] = bias[bm * 128 + tid];

    const __half* gA = g_aprime + (size_t)(bm * 128) * KVIRT;
    const size_t brow = ((size_t)img * NPAD + bn * 128) * KREAL;

    float acc[4][4][4];
#pragma unroll
    for (int i = 0; i < 4; i++)
#pragma unroll
        for (int j = 0; j < 4; j++)
#pragma unroll
            for (int e = 0; e < 4; e++) acc[i][j][e] = 0.f;

    const int lr = tid >> 3, lc = tid & 7;
    const int lcs = ((lc ^ (lr & 7)) * 16);

    const int ra = warp_m * 64 + (lane & 15);
    const int kha = (lane >> 4);
    const int xa = ra & 7;
    const int q8 = lane >> 3;
    const int xb = lane & 7;

#define LOAD_STAGE(T, S) do { \
    uint32_t sa_ = base + (S) * STGB; \
    int k0_ = (T) * KCHUNK; \
    const __half* gAr_ = gA + k0_ + lc * 8; \
    _Pragma("unroll") \
    for (int i_ = 0; i_ < 4; i_++) { \
        int r_ = lr + 32 * i_; \
        cpa16(sa_ + r_ * 128 + lcs, gAr_ + (size_t)r_ * KVIRT); \
    } \
    int blk_ = (T) / 72; \
    int kr_ = ((T) - blk_ * 72) * KCHUNK; \
    const __half* gBsel_ = (blk_ == 2) ? g_bl : ((blk_ == 1 || blk_ == 4) ? g_bm : g_bh); \
    const __half* gBr_ = gBsel_ + brow + kr_ + lc * 8; \
    uint32_t sb_ = sa_ + ASTG; \
    _Pragma("unroll") \
    for (int i_ = 0; i_ < 4; i_++) { \
        int r_ = lr + 32 * i_; \
        cpa16(sb_ + r_ * 128 + lcs, gBr_ + (size_t)r_ * KREAL); \
    } \
    asm volatile("cp.async.commit_group;" ::: "memory"); \
} while (0)

    LOAD_STAGE(0, 0);
    LOAD_STAGE(1, 1);

    int sCmp = 0, sLoad = 2;
    for (int t = 0; t < NCHUNK; t++) {
        if (t < NCHUNK - 2) asm volatile("cp.async.wait_group 1;" ::: "memory");
        else                asm volatile("cp.async.wait_group 0;" ::: "memory");
        __syncthreads();

        int blkc = t / 72;
        float cscale = (blkc == 0) ? 1.f
                     : ((blkc == 1 || blkc == 3) ? SC1I : SC2I);

        uint32_t sa = base + sCmp * STGB;
        uint32_t sb = sa + ASTG;
#pragma unroll
        for (int mt = 0; mt < 4; mt++) {
            uint32_t a[4][4];
            const int rA = ra + mt * 16;
#pragma unroll
            for (int kk = 0; kk < 4; kk++)
                LDSM_X4(a[kk], sa + rA * 128 + (((kk * 2 + kha) ^ xa) * 16));
#pragma unroll
            for (int nt = 0; nt < 4; nt++) {
                const int rB = warp_n * 32 + nt * 8 + xb;
                uint32_t b[8];
                LDSM_X4(b,     sb + rB * 128 + (((0 + q8) ^ xb) * 16));
                LDSM_X4(b + 4, sb + rB * 128 + (((4 + q8) ^ xb) * 16));
                float tmp[4];
                mma16816_z(tmp, a[0], b);
                mma16816(tmp, a[1], b + 2);
                mma16816(tmp, a[2], b + 4);
                mma16816(tmp, a[3], b + 6);
#pragma unroll
                for (int e = 0; e < 4; e++)
                    acc[mt][nt][e] = fmaf(tmp[e], cscale, acc[mt][nt][e]);
            }
        }

        if (t + 2 < NCHUNK) LOAD_STAGE(t + 2, sLoad);
        if (++sLoad == 3) sLoad = 0;
        if (++sCmp == 3) sCmp = 0;
    }

    // epilogue: transpose through smem (stride 129), bias + relu, coalesced store
    __syncthreads();
    float* tb = (float*)dsm;
#pragma unroll
    for (int mt = 0; mt < 4; mt++)
#pragma unroll
        for (int nt = 0; nt < 4; nt++) {
            int m = warp_m * 64 + mt * 16 + (lane >> 2);
            int n = warp_n * 32 + nt * 8 + 2 * (lane & 3);
            tb[m * 129 + n]           = acc[mt][nt][0];
            tb[m * 129 + n + 1]       = acc[mt][nt][1];
            tb[(m + 8) * 129 + n]     = acc[mt][nt][2];
            tb[(m + 8) * 129 + n + 1] = acc[mt][nt][3];
        }
    __syncthreads();

    const int j = tid >> 1, half = tid & 1;
    const int p = bn * 128 + j;
    if (p < PXN) {
        float* dst = g_inter + ((size_t)(img * PXN + p)) * 512 + bm * 128 + half * 64;
#pragma unroll
        for (int i = 0; i < 16; i++) {
            int m0 = half * 64 + i * 4;
            float4 v;
            v.x = fmaxf(tb[(m0 + 0) * 129 + j] + sbias[m0 + 0], 0.f);
            v.y = fmaxf(tb[(m0 + 1) * 129 + j] + sbias[m0 + 1], 0.f);
            v.z = fmaxf(tb[(m0 + 2) * 129 + j] + sbias[m0 + 2], 0.f);
            v.w = fmaxf(tb[(m0 + 3) * 129 + j] + sbias[m0 + 3], 0.f);
            *(float4*)(dst + i * 4) = v;
        }
    }
#undef LOAD_STAGE
}

// ================= key padding =================
__global__ void fill_keys() {
    int t = blockIdx.x * blockDim.x + threadIdx.x;
    if (t < N_IMG * NSORT) g_keys[t] = ~0ull;
}

// ================= heads =================
__global__ __launch_bounds__(448)
void heads_kernel(const float* __restrict__ WS, const float* __restrict__ BS,
                  const float* __restrict__ WL, const float* __restrict__ BL,
                  float* __restrict__ out,
                  const unsigned* __restrict__ pimh, const unsigned* __restrict__ pimw) {
    extern __shared__ float sm[];
    float* wsm = sm;            // 54 rows, stride 516
    float* vsm = sm + 27864;    // 8 rows, stride 516
    float* bsm = sm + 31992;
    float* res = sm + 32056;
    const int t = threadIdx.x;
    const int gp0 = blockIdx.x * 8;

    for (int i = t; i < 18 * 512; i += 448) { int r = i >> 9, c = i & 511; wsm[r * 516 + c] = WS[i]; }
    for (int i = t; i < 36 * 512; i += 448) { int r = i >> 9, c = i & 511; wsm[(18 + r) * 516 + c] = WL[i]; }
    if (t < 18) bsm[t] = BS[t]; else if (t < 54) bsm[t] = BL[t - 18];
    for (int i = t; i < 8 * 512; i += 448) {
        int p = i >> 9, c = i & 511;
        int gp = gp0 + p;
        vsm[p * 516 + c] = (gp < 10000) ? g_inter[(size_t)gp * 512 + c] : 0.f;
    }
    __syncthreads();

    if (t < 432) {
        int o = t >> 3, px = t & 7;
        const float4* wv = (const float4*)(wsm + o * 516);
        const float4* vv = (const float4*)(vsm + px * 516);
        float acc = 0.f;
#pragma unroll 8
        for (int q = 0; q < 128; q++) {
            float4 w4 = wv[q], v4 = vv[q];
            acc += w4.x * v4.x + w4.y * v4.y + w4.z * v4.z + w4.w * v4.w;
        }
        res[px * 54 + o] = acc + bsm[o];
    }
    __syncthreads();

    if (t < 72) {
        int px = t / 9, a = t - px * 9;
        int gp = gp0 + px;
        if (gp < 10000) {
            float imh = readScalar(pimh), imw = readScalar(pimw);
            const float* rr = res + px * 54;
            int n = gp / 2500, p = gp - n * 2500;
            int y = p / 50, x = p - y * 50;
            float s0 = rr[2 * a], s1 = rr[2 * a + 1];
            float d0 = rr[18 + 4 * a + 0], d1 = rr[18 + 4 * a + 1];
            float d2 = rr[18 + 4 * a + 2], d3 = rr[18 + 4 * a + 3];
            float yy = (float)(y * 16), xx = (float)(x * 16);
            float ay1 = yy + cAy1[a], ay2 = yy + cAy2[a];
            float ax1 = xx + cAx1[a], ax2 = xx + cAx2[a];
            float ah = ay2 - ay1, aw = ax2 - ax1;
            float acy = ay1 + 0.5f * ah, acx = ax1 + 0.5f * aw;
            float cy = d0 * ah + acy, cx = d1 * aw + acx;
            float bh = expf(d2) * ah, bw = expf(d3) * aw;
            float y1 = fminf(fmaxf(cy - 0.5f * bh, 0.f), imh);
            float y2 = fminf(fmaxf(cy + 0.5f * bh, 0.f), imh);
            float x1 = fminf(fmaxf(cx - 0.5f * bw, 0.f), imw);
            float x2 = fminf(fmaxf(cx + 0.5f * bw, 0.f), imw);
            bool valid = ((y2 - y1) >= 16.f) && ((x2 - x1) >= 16.f);
            float fg = 1.f / (1.f + expf(s0 - s1));
            int ridx = p * 9 + a;
            int gi = n * 22500 + ridx;
            out[OFF_LOC + (size_t)gi * 4 + 0] = d0;
            out[OFF_LOC + (size_t)gi * 4 + 1] = d1;
            out[OFF_LOC + (size_t)gi * 4 + 2] = d2;
            out[OFF_LOC + (size_t)gi * 4 + 3] = d3;
            out[OFF_SCORE + (size_t)gi * 2 + 0] = s0;
            out[OFF_SCORE + (size_t)gi * 2 + 1] = s1;
            float* bx = g_boxes + (size_t)gi * 4;
            bx[0] = y1; bx[1] = x1; bx[2] = y2; bx[3] = x2;
            float sc = valid ? fg : __int_as_float(0xff800000);
            g_keys[(size_t)n * NSORT + ridx] = packKey(sc, (unsigned)ridx);
        }
    }
}

// ================= anchors =================
__global__ void write_anchors(float* __restrict__ out) {
    int r = blockIdx.x * 256 + threadIdx.x;
    if (r < RTOT) {
        int a = r % 9; int pix = r / 9;
        int y = pix / 50, x = pix - y * 50;
        float yy = (float)(y * 16), xx = (float)(x * 16);
        out[OFF_ANC + (size_t)r * 4 + 0] = yy + cAy1[a];
        out[OFF_ANC + (size_t)r * 4 + 1] = xx + cAx1[a];
        out[OFF_ANC + (size_t)r * 4 + 2] = yy + cAy2[a];
        out[OFF_ANC + (size_t)r * 4 + 3] = xx + cAx2[a];
    }
}

// ================= bitonic sort =================
__global__ __launch_bounds__(1024)
void sort_local() {
    __shared__ unsigned long long s[4096];
    int chunk = blockIdx.x; int img = chunk >> 3; int cb = (chunk & 7) * 4096;
    unsigned long long* g = g_keys + (size_t)img * NSORT + cb;
    int t = threadIdx.x;
#pragma unroll
    for (int q = 0; q < 4; q++) s[t + q * 1024] = g[t + q * 1024];
    __syncthreads();
    for (int k = 2; k <= 4096; k <<= 1) {
        for (int j = k >> 1; j > 0; j >>= 1) {
#pragma unroll
            for (int q = 0; q < 2; q++) {
                int pid = t + q * 1024;
                int i = ((pid & ~(j - 1)) << 1) | (pid & (j - 1));
                int pr = i | j;
                bool asc = (((cb + i) & k) == 0);
                unsigned long long a = s[i], b = s[pr];
                if ((a > b) == asc) { s[i] = b; s[pr] = a; }
            }
            __syncthreads();
        }
    }
#pragma unroll
    for (int q = 0; q < 4; q++) g[t + q * 1024] = s[t + q * 1024];
}

__global__ void sort_gstep(int k, int j) {
    int t = blockIdx.x * blockDim.x + threadIdx.x;
    int n = t >> 14; int tt = t & 16383;
    int i = ((tt & ~(j - 1)) << 1) | (tt & (j - 1));
    bool asc = ((i & k) == 0);
    unsigned long long* g = g_keys + (size_t)n * NSORT;
    unsigned long long a = g[i], b = g[i | j];
    if ((a > b) == asc) { g[i] = b; g[i | j] = a; }
}

__global__ __launch_bounds__(1024)
void sort_lfinish(int k) {
    __shared__ unsigned long long s[4096];
    int chunk = blockIdx.x; int img = chunk >> 3; int cb = (chunk & 7) * 4096;
    unsigned long long* g = g_keys + (size_t)img * NSORT + cb;
    int t = threadIdx.x;
#pragma unroll
    for (int q = 0; q < 4; q++) s[t + q * 1024] = g[t + q * 1024];
    __syncthreads();
    bool asc = ((cb & k) == 0);
    for (int j = 2048; j > 0; j >>= 1) {
#pragma unroll
        for (int q = 0; q < 2; q++) {
            int pid = t + q * 1024;
            int i = ((pid & ~(j - 1)) << 1) | (pid & (j - 1));
            int pr = i | j;
            unsigned long long a = s[i], b = s[pr];
            if ((a > b) == asc) { s[i] = b; s[pr] = a; }
        }
        __syncthreads();
    }
#pragma unroll
    for (int q = 0; q < 4; q++) g[t + q * 1024] = s[t + q * 1024];
}

// ================= gather top-6000 =================
__global__ void gather_top() {
    int t = blockIdx.x * blockDim.x + threadIdx.x;
    if (t >= N_IMG * NBEF) return;
    int n = t / NBEF;
    unsigned long long key = g_keys[(size_t)n * NSORT + (t - n * NBEF)];
    unsigned idx = (unsigned)key;
    unsigned hi = (unsigned)(key >> 32);
    bool valid = hi < 0x80000000u;
    float4 b = make_float4(0, 0, 0, 0);
    if (idx < RTOT) b = *(const float4*)(g_boxes + ((size_t)n * RTOT + idx) * 4);
    *(float4*)(g_sboxes + (size_t)t * 4) = b;
    g_valid[t] = valid ? 1 : 0;
}

// ================= NMS bitmask =================
__global__ __launch_bounds__(64)
void nms_mask() {
    int cb = blockIdx.x, rb = blockIdx.y, n = blockIdx.z;
    int t = threadIdx.x;
    int i = rb * 64 + t;
    if (cb < rb) {
        if (i < NBEF) g_mask[((size_t)(n * NBEF) + i) * WORDS + cb] = 0ull;
        return;
    }
    __shared__ float4 cbox[64];
    int j0 = cb * 64;
    float4 b = make_float4(0, 0, 0, 0);
    if (j0 + t < NBEF) b = *(const float4*)(g_sboxes + ((size_t)n * NBEF + j0 + t) * 4);
    cbox[t] = b;
    __syncthreads();
    if (i >= NBEF) return;
    float4 r = *(const float4*)(g_sboxes + ((size_t)n * NBEF + i) * 4);
    float ra = (r.z - r.x) * (r.w - r.y);
    unsigned long long m = 0;
#pragma unroll 8
    for (int c = 0; c < 64; c++) {
        int j = j0 + c;
        float4 q = cbox[c];
        float ty = fmaxf(r.x, q.x), tx = fmaxf(r.y, q.y);
        float by = fminf(r.z, q.z), bx = fminf(r.w, q.w);
        float inter = fmaxf(by - ty, 0.f) * fmaxf(bx - tx, 0.f);
        float qa = (q.z - q.x) * (q.w - q.y);
        float iou = inter / (ra + qa - inter + 1e-9f);
        if (j > i && iou > 0.7f) m |= (1ull << c);
    }
    g_mask[((size_t)(n * NBEF) + i) * WORDS + cb] = m;
}

// ================= NMS serial scan =================
__global__ void nms_scan(float* __restrict__ out) {
    int n = blockIdx.x; int lane = threadIdx.x;
    unsigned long long rem[3] = {0, 0, 0};
    __shared__ int kl[NAFT];
    int kc = 0;
    for (int i = 0; i < NBEF && kc < NAFT; ++i) {
        int wi = i >> 6; int slot = wi >> 5; int owner = wi & 31;
        unsigned long long myw = (slot == 0) ? rem[0] : ((slot == 1) ? rem[1] : rem[2]);
        unsigned long long w = __shfl_sync(0xffffffffu, myw, owner);
        bool removed = (w >> (i & 63)) & 1ull;
        if (!removed && g_valid[(size_t)n * NBEF + i]) {
            if (lane == 0) kl[kc] = i;
            kc++;
            const unsigned long long* mr = g_mask + ((size_t)(n * NBEF) + i) * WORDS;
#pragma unroll
            for (int s = 0; s < 3; s++) {
                int ww = lane + 32 * s;
                if (ww < WORDS) rem[s] |= mr[ww];
            }
        }
    }
    __syncwarp();
    for (int r = lane; r < NAFT; r += 32) {
        float4 b = make_float4(0, 0, 0, 0);
        if (r < kc) b = *(const float4*)(g_sboxes + ((size_t)n * NBEF + kl[r]) * 4);
        float* dst = out + OFF_ROIS + (size_t)(n * NAFT + r) * 4;
        dst[0] = b.x; dst[1] = b.y; dst[2] = b.z; dst[3] = b.w;
        out[OFF_IDX + n * NAFT + r] = (float)n;
    }
}

// ================= launch =================
extern "C" void kernel_launch(void* const* d_in, const int* in_sizes, int n_in,
                              void* d_out, int out_size) {
    const float* x  = (const float*)d_in[0];
    const float* w1 = (const float*)d_in[1];
    const float* b1 = (const float*)d_in[2];
    const float* ws = (const float*)d_in[3];
    const float* bs = (const float*)d_in[4];
    const float* wl = (const float*)d_in[5];
    const float* bl = (const float*)d_in[6];
    const unsigned* ih = (const unsigned*)d_in[7];
    const unsigned* iw = (const unsigned*)d_in[8];
    float* out = (float*)d_out;

    cudaFuncSetAttribute(conv_mma, cudaFuncAttributeMaxDynamicSharedMemorySize, SMEM_CONV);
    cudaFuncSetAttribute(heads_kernel, cudaFuncAttributeMaxDynamicSharedMemorySize, SMEM_HEADS);

    wsplit<<<6912, 256>>>(w1);
    im2col_split<<<23040, 256>>>(x);
    fill_keys<<<512, 256>>>();
    conv_mma<<<dim3(4, 20, 4), 256, SMEM_CONV>>>(b1);
    heads_kernel<<<1250, 448, SMEM_HEADS>>>(ws, bs, wl, bl, out, ih, iw);
    write_anchors<<<88, 256>>>(out);

    sort_local<<<32, 1024>>>();
    sort_gstep<<<256, 256>>>(8192, 4096);
    sort_lfinish<<<32, 1024>>>(8192);
    sort_gstep<<<256, 256>>>(16384, 8192);
    sort_gstep<<<256, 256>>>(16384, 4096);
    sort_lfinish<<<32, 1024>>>(16384);
    sort_gstep<<<256, 256>>>(32768, 16384);
    sort_gstep<<<256, 256>>>(32768, 8192);
    sort_gstep<<<256, 256>>>(32768, 4096);
    sort_lfinish<<<32, 1024>>>(32768);

    gather_top<<<94, 256>>>();
    nms_mask<<<dim3(WORDS, WORDS, N_IMG), 64>>>();
    nms_scan<<<N_IMG, 32>>>(out);
}